// round 7
// baseline (speedup 1.0000x reference)
#include <cuda_runtime.h>

// ---------------------------------------------------------------------------
// MixingBlock: s = softmax((x Wq)(sl Wk)^T * scale) @ sl,  w = the softmax
// Restructure: dots = x @ KQ^T with KQ = scale * (sl Wk) Wq^T  (tiny [128,180])
// Pipeline: p1 (sl@Wk partials) -> p1r (reduce, zero KQT) -> p2 (KQ, atomic)
//           -> cf (fused dots+softmax+w  +  s = w@sl)
// ---------------------------------------------------------------------------

#define NB 4
#define NR 8192
#define NS 32
#define IN_DIM 180
#define SD 1536
#define AD 1536
#define BS (NB*NS)          // 128
#define KS 24               // d-split for p1
#define KCHUNK (SD/KS)      // 64
#define AC 24               // a-chunks for p2
#define ACHUNK (AD/AC)      // 64
#define JT 16               // j-tile for p2

typedef unsigned long long ull;

__device__ float g_kpart[KS][BS][AD];     // p1 partials
__device__ float g_kred[BS][AD];          // reduced k
__device__ float g_KQT[IN_DIM][BS];       // KQ transposed (scale folded in)

// ---- packed f32x2 helpers -------------------------------------------------
__device__ __forceinline__ ull fpack(float x, float y) {
    ull r; asm("mov.b64 %0, {%1, %2};" : "=l"(r) : "f"(x), "f"(y)); return r;
}
__device__ __forceinline__ float2 funpack(ull v) {
    float2 r; asm("mov.b64 {%0, %1}, %2;" : "=f"(r.x), "=f"(r.y) : "l"(v)); return r;
}
__device__ __forceinline__ ull ffma2(ull a, ull b, ull c) {
    ull d; asm("fma.rn.f32x2 %0, %1, %2, %3;" : "=l"(d) : "l"(a), "l"(b), "l"(c)); return d;
}
__device__ __forceinline__ ull d2u(double d) { return __double_as_longlong(d); }
__device__ __forceinline__ double u2d(ull v) { return __longlong_as_double(v); }

__device__ __forceinline__ void cp_async16(void* smem_dst, const void* gsrc) {
    unsigned sa = (unsigned)__cvta_generic_to_shared(smem_dst);
    asm volatile("cp.async.cg.shared.global [%0], [%1], 16;" :: "r"(sa), "l"(gsrc));
}
__device__ __forceinline__ void cp_commit() {
    asm volatile("cp.async.commit_group;");
}
template<int N> __device__ __forceinline__ void cp_wait() {
    asm volatile("cp.async.wait_group %0;" :: "n"(N));
}

// ---------------------------------------------------------------------------
// P1: g_kpart[p][m][n] = sum_{d in chunk p} sl[m][d] * Wk[d][n]
// grid (6 n-tiles of 256, 4 m-tiles of 32, 24 d-chunks of 64), 128 thr.
// ---------------------------------------------------------------------------
__global__ __launch_bounds__(128) void p1_kernel(const float* __restrict__ sl,
                                                 const float* __restrict__ Wk) {
    const int n0 = blockIdx.x * 256;
    const int m0 = blockIdx.y * 32;
    const int p  = blockIdx.z;
    const int d0 = p * KCHUNK;
    __shared__ float sWk[16][256];
    __shared__ ull   sslp[16][33];
    const int tid  = threadIdx.x;
    const int warp = tid >> 5, lane = tid & 31;
    const int mbase = warp * 8;

    ull acc[8][4];
    #pragma unroll
    for (int i = 0; i < 8; i++)
        #pragma unroll
        for (int q = 0; q < 4; q++) acc[i][q] = 0ULL;

    for (int kk = 0; kk < KCHUNK; kk += 16) {
        __syncthreads();
        #pragma unroll
        for (int t = 0; t < 8; t++) {
            int idx = t * 128 + tid;
            int dd = idx >> 6, nq = idx & 63;
            *(float4*)&sWk[dd][nq * 4] =
                *(const float4*)&Wk[(size_t)(d0 + kk + dd) * AD + n0 + nq * 4];
        }
        #pragma unroll
        for (int t = 0; t < 4; t++) {
            int idx = t * 128 + tid;
            int m = idx >> 4, dd = idx & 15;
            float v = sl[(size_t)(m0 + m) * SD + d0 + kk + dd];
            sslp[dd][m] = fpack(v, v);
        }
        __syncthreads();
        #pragma unroll
        for (int dd = 0; dd < 16; dd++) {
            double2 a01 = *(const double2*)&sWk[dd][lane * 4];
            double2 a23 = *(const double2*)&sWk[dd][128 + lane * 4];
            ull A0 = d2u(a01.x), A1 = d2u(a01.y), A2 = d2u(a23.x), A3 = d2u(a23.y);
            #pragma unroll
            for (int i = 0; i < 8; i++) {
                ull wv = sslp[dd][mbase + i];
                acc[i][0] = ffma2(A0, wv, acc[i][0]);
                acc[i][1] = ffma2(A1, wv, acc[i][1]);
                acc[i][2] = ffma2(A2, wv, acc[i][2]);
                acc[i][3] = ffma2(A3, wv, acc[i][3]);
            }
        }
    }
    #pragma unroll
    for (int i = 0; i < 8; i++) {
        int m = m0 + mbase + i;
        float* dst = &g_kpart[p][m][n0 + lane * 4];
        *(double2*)dst         = make_double2(u2d(acc[i][0]), u2d(acc[i][1]));
        *(double2*)(dst + 128) = make_double2(u2d(acc[i][2]), u2d(acc[i][3]));
    }
}

// ---------------------------------------------------------------------------
// P1R: g_kred = sum_p g_kpart[p]; also zeros g_KQT for p2's atomics.
// ---------------------------------------------------------------------------
__global__ __launch_bounds__(256) void p1r_kernel() {
    int gid = blockIdx.x * 256 + threadIdx.x;    // over 128*1536/4 = 49152
    if (gid < IN_DIM * BS) (&g_KQT[0][0])[gid] = 0.f;
    const float4* src = (const float4*)&g_kpart[0][0][0];
    float4* dst = (float4*)&g_kred[0][0];
    const int stride = (BS * AD) / 4;
    float4 a = make_float4(0.f, 0.f, 0.f, 0.f);
    #pragma unroll
    for (int p = 0; p < KS; p++) {
        float4 v = src[(size_t)p * stride + gid];
        a.x += v.x; a.y += v.y; a.z += v.z; a.w += v.w;
    }
    dst[gid] = a;
}

// ---------------------------------------------------------------------------
// P2: g_KQT[j][m] += scale * sum_{a in chunk} kred[m][a] * Wq[j][a]
// grid (12 j-tiles of 16, 24 a-chunks of 64), 256 thr. RED.F32 accumulation.
// ---------------------------------------------------------------------------
__global__ __launch_bounds__(256) void p2_kernel(const float* __restrict__ Wq) {
    const int j0 = blockIdx.x * JT;
    const int ac = blockIdx.y;
    const int a0 = ac * ACHUNK;
    __shared__ float ksm[64][130];    // [a][m], padded
    __shared__ ull   wqs[64][18];     // splatted Wq [a][jj], padded
    const int tid = threadIdx.x;
    const int mp = tid & 63;          // m-pair: m = 2*mp
    const int jg = tid >> 6;          // j = j0 + jg*4 + {0..3}

    #pragma unroll
    for (int t = 0; t < 8; t++) {     // transpose kred chunk into ksm
        int idx = t * 256 + tid;
        int m = idx >> 4, aq = idx & 15;
        float4 v = *(const float4*)&g_kred[m][a0 + aq * 4];
        ksm[aq * 4 + 0][m] = v.x;
        ksm[aq * 4 + 1][m] = v.y;
        ksm[aq * 4 + 2][m] = v.z;
        ksm[aq * 4 + 3][m] = v.w;
    }
    const float scale = rsqrtf((float)AD);
    #pragma unroll
    for (int t = 0; t < 4; t++) {     // Wq splats
        int idx = t * 256 + tid;
        int jj = idx >> 6, a = idx & 63;
        int j = j0 + jj;
        float v = (j < IN_DIM) ? Wq[(size_t)j * AD + a0 + a] * scale : 0.f;
        wqs[a][jj] = fpack(v, v);
    }
    __syncthreads();

    ull acc[4] = {0ULL, 0ULL, 0ULL, 0ULL};
    #pragma unroll 4
    for (int a = 0; a < ACHUNK; a++) {
        ull kp = *(const ull*)&ksm[a][2 * mp];
        double2 w01 = *(const double2*)&wqs[a][jg * 4];
        double2 w23 = *(const double2*)&wqs[a][jg * 4 + 2];
        acc[0] = ffma2(kp, d2u(w01.x), acc[0]);
        acc[1] = ffma2(kp, d2u(w01.y), acc[1]);
        acc[2] = ffma2(kp, d2u(w23.x), acc[2]);
        acc[3] = ffma2(kp, d2u(w23.y), acc[3]);
    }
    #pragma unroll
    for (int q = 0; q < 4; q++) {
        int j = j0 + jg * 4 + q;
        if (j < IN_DIM) {
            float2 v = funpack(acc[q]);
            atomicAdd(&g_KQT[j][2 * mp], v.x);
            atomicAdd(&g_KQT[j][2 * mp + 1], v.y);
        }
    }
}

// ---------------------------------------------------------------------------
// CF: fused c1+c2. One block = 128 rows, 256 thr, 2 blocks/SM, single wave.
// Phase A: dots (x @ KQ^T) + softmax -> w_out + splatted wsp in smem.
// Phase B: s_out = w @ sl over 12 d-tiles, cp.async double-buffered.
// smem: xs 23040 | kqt 23040 | slbuf 32768 | wsp 32768  = 111616 B
// ---------------------------------------------------------------------------
#define CF_SMEM 111616
#define XS_OFF   0
#define KQT_OFF  23040
#define SLB_OFF  46080
#define WSP_OFF  78848

__global__ __launch_bounds__(256, 2) void cf_kernel(const float* __restrict__ x,
                                                    const float* __restrict__ sl,
                                                    float* __restrict__ w_out,
                                                    float* __restrict__ s_out) {
    extern __shared__ char smraw[];
    float* xs    = (float*)(smraw + XS_OFF);    // [32][180]
    float* kqt   = (float*)(smraw + KQT_OFF);   // [180][32]
    float* slbuf = (float*)(smraw + SLB_OFF);   // [2][32][128]
    ull*   wsp   = (ull*)  (smraw + WSP_OFF);   // [128][32]

    const int tid  = threadIdx.x;
    const int warp = tid >> 5, lane = tid & 31;
    const int row0 = blockIdx.x * 128;
    const int b    = row0 >> 13;

    // kick off sl tile prefetch for d-tiles 0 and 1 (independent of phase A)
    #pragma unroll
    for (int t = 0; t < 2; t++) {
        for (int k = tid; k < 1024; k += 256) {
            int s = k >> 5, dq = k & 31;
            cp_async16(&slbuf[t * 4096 + s * 128 + dq * 4],
                       &sl[(size_t)(b * NS + s) * SD + t * 128 + dq * 4]);
        }
        cp_commit();
    }

    // fill kqt (coalesced from g_KQT)
    for (int idx = tid; idx < IN_DIM * NS; idx += 256) {
        int j = idx >> 5, s = idx & 31;
        kqt[j * 32 + s] = g_KQT[j][b * NS + s];
    }

    // ---- Phase A: 4 groups of 32 rows ----
    const int sg = tid & 7;     // slots sg*4 + {0..3}
    const int rr = tid >> 3;    // local row 0..31
    for (int g = 0; g < 4; g++) {
        __syncthreads();        // xs reuse + (g==0) kqt visibility
        for (int idx = tid; idx < 32 * 45; idx += 256) {
            int r = idx / 45, q = idx - r * 45;
            *(float4*)&xs[r * IN_DIM + q * 4] =
                *(const float4*)&x[(size_t)(row0 + g * 32 + r) * IN_DIM + q * 4];
        }
        __syncthreads();

        ull acc0 = 0ULL, acc1 = 0ULL;
        #pragma unroll 6
        for (int j = 0; j < IN_DIM; j++) {
            double2 kd = *(const double2*)&kqt[j * 32 + sg * 4];
            float xv = xs[rr * IN_DIM + j];
            ull xd = fpack(xv, xv);
            acc0 = ffma2(d2u(kd.x), xd, acc0);
            acc1 = ffma2(d2u(kd.y), xd, acc1);
        }
        float2 d01 = funpack(acc0), d23 = funpack(acc1);
        float m = fmaxf(fmaxf(d01.x, d01.y), fmaxf(d23.x, d23.y));
        m = fmaxf(m, __shfl_xor_sync(0xffffffffu, m, 1));
        m = fmaxf(m, __shfl_xor_sync(0xffffffffu, m, 2));
        m = fmaxf(m, __shfl_xor_sync(0xffffffffu, m, 4));
        float e0 = __expf(d01.x - m), e1 = __expf(d01.y - m);
        float e2 = __expf(d23.x - m), e3 = __expf(d23.y - m);
        float sum = (e0 + e1) + (e2 + e3);
        sum += __shfl_xor_sync(0xffffffffu, sum, 1);
        sum += __shfl_xor_sync(0xffffffffu, sum, 2);
        sum += __shfl_xor_sync(0xffffffffu, sum, 4);
        float inv = 1.0f / sum;
        float w0 = e0 * inv, w1 = e1 * inv, w2 = e2 * inv, w3 = e3 * inv;
        *(float4*)&w_out[(size_t)(row0 + g * 32 + rr) * NS + sg * 4] =
            make_float4(w0, w1, w2, w3);
        ull* wd = &wsp[(g * 32 + rr) * NS + sg * 4];
        wd[0] = fpack(w0, w0); wd[1] = fpack(w1, w1);
        wd[2] = fpack(w2, w2); wd[3] = fpack(w3, w3);
    }

    // ---- Phase B: 12 d-tiles, warp = 16 rows x 128 d ----
    const int rbase = warp * 16;
    for (int dt = 0; dt < 12; dt++) {
        if (dt < 11) cp_wait<1>(); else cp_wait<0>();
        __syncthreads();                       // tile ready + wsp ready (dt==0)
        const float* sls = slbuf + (dt & 1) * 4096;

        ull acc[16][2];
        #pragma unroll
        for (int i = 0; i < 16; i++) { acc[i][0] = 0ULL; acc[i][1] = 0ULL; }

        #pragma unroll 2
        for (int s = 0; s < NS; s += 2) {
            double2 av = *(const double2*)&sls[s * 128 + lane * 4];
            double2 bv = *(const double2*)&sls[(s + 1) * 128 + lane * 4];
            ull A0 = d2u(av.x), A1 = d2u(av.y);
            ull B0 = d2u(bv.x), B1 = d2u(bv.y);
            #pragma unroll
            for (int i = 0; i < 16; i++) {
                double2 wp = *(const double2*)&wsp[(rbase + i) * NS + s];
                ull w0 = d2u(wp.x), w1 = d2u(wp.y);
                acc[i][0] = ffma2(A0, w0, acc[i][0]);
                acc[i][1] = ffma2(A1, w0, acc[i][1]);
                acc[i][0] = ffma2(B0, w1, acc[i][0]);
                acc[i][1] = ffma2(B1, w1, acc[i][1]);
            }
        }
        #pragma unroll
        for (int i = 0; i < 16; i++) {
            float* dst = s_out + (size_t)(row0 + rbase + i) * SD + dt * 128 + lane * 4;
            *(double2*)dst = make_double2(u2d(acc[i][0]), u2d(acc[i][1]));
        }
        __syncthreads();                       // everyone done reading buffer
        if (dt + 2 < 12) {
            int t = dt + 2;
            for (int k = tid; k < 1024; k += 256) {
                int s = k >> 5, dq = k & 31;
                cp_async16(&slbuf[(t & 1) * 4096 + s * 128 + dq * 4],
                           &sl[(size_t)(b * NS + s) * SD + t * 128 + dq * 4]);
            }
            cp_commit();
        }
    }
}

// ---------------------------------------------------------------------------
extern "C" void kernel_launch(void* const* d_in, const int* in_sizes, int n_in,
                              void* d_out, int out_size) {
    const float* x  = (const float*)d_in[0];   // [4,8192,180]
    const float* sl = (const float*)d_in[1];   // [4,32,1536]
    const float* Wq = (const float*)d_in[2];   // [180,1536]
    const float* Wk = (const float*)d_in[3];   // [1536,1536]
    float* out   = (float*)d_out;
    float* s_out = out;                               // [4,8192,1536]
    float* w_out = out + (size_t)NB * NR * SD;        // [4,8192,32]

    static int attr_done = 0;
    if (!attr_done) {
        cudaFuncSetAttribute(cf_kernel,
                             cudaFuncAttributeMaxDynamicSharedMemorySize, CF_SMEM);
        attr_done = 1;
    }

    p1_kernel<<<dim3(AD / 256, BS / 32, KS), 128>>>(sl, Wk);
    p1r_kernel<<<(BS * AD / 4) / 256, 256>>>();
    p2_kernel<<<dim3(192 / JT, AC), 256>>>(Wq);
    cf_kernel<<<(NB * NR) / 128, 256, CF_SMEM>>>(x, sl, w_out, s_out);
}

// round 8
// speedup vs baseline: 1.1723x; 1.1723x over previous
#include <cuda_runtime.h>

// ---------------------------------------------------------------------------
// MixingBlock: s = softmax((x Wq)(sl Wk)^T * scale) @ sl,  w = the softmax
// Restructure: dots = x @ KQ^T with KQ = scale * (sl Wk) Wq^T  (tiny [128,180])
// Pipeline: p1 -> p1r (reduce + zero KQT) -> p2 (atomic KQ) -> c1 -> c2
// ---------------------------------------------------------------------------

#define NB 4
#define NR 8192
#define NS 32
#define IN_DIM 180
#define SD 1536
#define AD 1536
#define BS (NB*NS)          // 128
#define KS 24               // d-split for p1
#define KCHUNK (SD/KS)      // 64
#define AC 24               // a-chunks for p2
#define ACHUNK (AD/AC)      // 64
#define JT 16               // j-tile for p2

typedef unsigned long long ull;

__device__ float g_kpart[KS][BS][AD];     // p1 partials
__device__ float g_kred[BS][AD];          // reduced k
__device__ float g_KQT[IN_DIM][BS];       // KQ transposed (scale folded in)

// ---- packed f32x2 helpers -------------------------------------------------
__device__ __forceinline__ ull fpack(float x, float y) {
    ull r; asm("mov.b64 %0, {%1, %2};" : "=l"(r) : "f"(x), "f"(y)); return r;
}
__device__ __forceinline__ float2 funpack(ull v) {
    float2 r; asm("mov.b64 {%0, %1}, %2;" : "=f"(r.x), "=f"(r.y) : "l"(v)); return r;
}
__device__ __forceinline__ ull ffma2(ull a, ull b, ull c) {
    ull d; asm("fma.rn.f32x2 %0, %1, %2, %3;" : "=l"(d) : "l"(a), "l"(b), "l"(c)); return d;
}
__device__ __forceinline__ ull d2u(double d) { return __double_as_longlong(d); }
__device__ __forceinline__ double u2d(ull v) { return __longlong_as_double(v); }

// ---------------------------------------------------------------------------
// P1: g_kpart[p][m][n] = sum_{d in chunk p} sl[m][d] * Wk[d][n]
// grid (6 n-tiles of 256, 4 m-tiles of 32, 24 d-chunks of 64), 128 thr.
// ---------------------------------------------------------------------------
__global__ __launch_bounds__(128) void p1_kernel(const float* __restrict__ sl,
                                                 const float* __restrict__ Wk) {
    const int n0 = blockIdx.x * 256;
    const int m0 = blockIdx.y * 32;
    const int p  = blockIdx.z;
    const int d0 = p * KCHUNK;
    __shared__ float sWk[16][256];
    __shared__ ull   sslp[16][33];
    const int tid  = threadIdx.x;
    const int warp = tid >> 5, lane = tid & 31;
    const int mbase = warp * 8;

    ull acc[8][4];
    #pragma unroll
    for (int i = 0; i < 8; i++)
        #pragma unroll
        for (int q = 0; q < 4; q++) acc[i][q] = 0ULL;

    for (int kk = 0; kk < KCHUNK; kk += 16) {
        __syncthreads();
        #pragma unroll
        for (int t = 0; t < 8; t++) {
            int idx = t * 128 + tid;
            int dd = idx >> 6, nq = idx & 63;
            *(float4*)&sWk[dd][nq * 4] =
                *(const float4*)&Wk[(size_t)(d0 + kk + dd) * AD + n0 + nq * 4];
        }
        #pragma unroll
        for (int t = 0; t < 4; t++) {
            int idx = t * 128 + tid;
            int m = idx >> 4, dd = idx & 15;
            float v = sl[(size_t)(m0 + m) * SD + d0 + kk + dd];
            sslp[dd][m] = fpack(v, v);
        }
        __syncthreads();
        #pragma unroll
        for (int dd = 0; dd < 16; dd++) {
            double2 a01 = *(const double2*)&sWk[dd][lane * 4];
            double2 a23 = *(const double2*)&sWk[dd][128 + lane * 4];
            ull A0 = d2u(a01.x), A1 = d2u(a01.y), A2 = d2u(a23.x), A3 = d2u(a23.y);
            #pragma unroll
            for (int i = 0; i < 8; i++) {
                ull wv = sslp[dd][mbase + i];
                acc[i][0] = ffma2(A0, wv, acc[i][0]);
                acc[i][1] = ffma2(A1, wv, acc[i][1]);
                acc[i][2] = ffma2(A2, wv, acc[i][2]);
                acc[i][3] = ffma2(A3, wv, acc[i][3]);
            }
        }
    }
    #pragma unroll
    for (int i = 0; i < 8; i++) {
        int m = m0 + mbase + i;
        float* dst = &g_kpart[p][m][n0 + lane * 4];
        *(double2*)dst         = make_double2(u2d(acc[i][0]), u2d(acc[i][1]));
        *(double2*)(dst + 128) = make_double2(u2d(acc[i][2]), u2d(acc[i][3]));
    }
}

// ---------------------------------------------------------------------------
// P1R: g_kred = sum_p g_kpart[p]; also zeros g_KQT for p2's atomics.
// ---------------------------------------------------------------------------
__global__ __launch_bounds__(256) void p1r_kernel() {
    int gid = blockIdx.x * 256 + threadIdx.x;    // over 128*1536/4 = 49152
    if (gid < IN_DIM * BS) (&g_KQT[0][0])[gid] = 0.f;
    const float4* src = (const float4*)&g_kpart[0][0][0];
    float4* dst = (float4*)&g_kred[0][0];
    const int stride = (BS * AD) / 4;
    float4 a = make_float4(0.f, 0.f, 0.f, 0.f);
    #pragma unroll
    for (int p = 0; p < KS; p++) {
        float4 v = src[(size_t)p * stride + gid];
        a.x += v.x; a.y += v.y; a.z += v.z; a.w += v.w;
    }
    dst[gid] = a;
}

// ---------------------------------------------------------------------------
// P2: g_KQT[j][m] += scale * sum_{a in chunk} kred[m][a] * Wq[j][a]
// grid (12 j-tiles of 16, 24 a-chunks of 64), 256 thr. RED.F32 accumulation.
// ---------------------------------------------------------------------------
__global__ __launch_bounds__(256) void p2_kernel(const float* __restrict__ Wq) {
    const int j0 = blockIdx.x * JT;
    const int ac = blockIdx.y;
    const int a0 = ac * ACHUNK;
    __shared__ float ksm[64][130];    // [a][m], padded
    __shared__ ull   wqs[64][18];     // splatted Wq [a][jj], padded
    const int tid = threadIdx.x;
    const int mp = tid & 63;          // m-pair: m = 2*mp
    const int jg = tid >> 6;          // j = j0 + jg*4 + {0..3}

    #pragma unroll
    for (int t = 0; t < 8; t++) {     // transpose kred chunk into ksm
        int idx = t * 256 + tid;
        int m = idx >> 4, aq = idx & 15;
        float4 v = *(const float4*)&g_kred[m][a0 + aq * 4];
        ksm[aq * 4 + 0][m] = v.x;
        ksm[aq * 4 + 1][m] = v.y;
        ksm[aq * 4 + 2][m] = v.z;
        ksm[aq * 4 + 3][m] = v.w;
    }
    const float scale = rsqrtf((float)AD);
    #pragma unroll
    for (int t = 0; t < 4; t++) {     // Wq splats
        int idx = t * 256 + tid;
        int jj = idx >> 6, a = idx & 63;
        int j = j0 + jj;
        float v = (j < IN_DIM) ? Wq[(size_t)j * AD + a0 + a] * scale : 0.f;
        wqs[a][jj] = fpack(v, v);
    }
    __syncthreads();

    ull acc[4] = {0ULL, 0ULL, 0ULL, 0ULL};
    #pragma unroll 4
    for (int a = 0; a < ACHUNK; a++) {
        ull kp = *(const ull*)&ksm[a][2 * mp];
        double2 w01 = *(const double2*)&wqs[a][jg * 4];
        double2 w23 = *(const double2*)&wqs[a][jg * 4 + 2];
        acc[0] = ffma2(kp, d2u(w01.x), acc[0]);
        acc[1] = ffma2(kp, d2u(w01.y), acc[1]);
        acc[2] = ffma2(kp, d2u(w23.x), acc[2]);
        acc[3] = ffma2(kp, d2u(w23.y), acc[3]);
    }
    #pragma unroll
    for (int q = 0; q < 4; q++) {
        int j = j0 + jg * 4 + q;
        if (j < IN_DIM) {
            float2 v = funpack(acc[q]);
            atomicAdd(&g_KQT[j][2 * mp], v.x);
            atomicAdd(&g_KQT[j][2 * mp + 1], v.y);
        }
    }
}

// ---------------------------------------------------------------------------
// C1: dots = x @ KQ^T (K=180), softmax over 32 slots, write w.
// grid 1024 (32 rows), 256 thr. Thread = 1 row x 4 slots.
// ---------------------------------------------------------------------------
#define C1_ROWS 32
__global__ __launch_bounds__(256) void c1_kernel(const float* __restrict__ x,
                                                 float* __restrict__ w_out) {
    const int row0 = blockIdx.x * C1_ROWS;
    const int b = row0 >> 13;
    __shared__ float xs[C1_ROWS][IN_DIM];     // 23 KB
    __shared__ float kqt[IN_DIM][32];         // 23 KB
    const int tid = threadIdx.x;

    for (int idx = tid; idx < C1_ROWS * 45; idx += 256) {
        int r = idx / 45, q = idx - r * 45;
        *(float4*)&xs[r][q * 4] =
            *(const float4*)&x[(size_t)(row0 + r) * IN_DIM + q * 4];
    }
    for (int idx = tid; idx < IN_DIM * NS; idx += 256) {
        int j = idx >> 5, s = idx & 31;
        kqt[j][s] = g_KQT[j][b * NS + s];
    }
    __syncthreads();

    const int sg = tid & 7;     // slots sg*4 + {0..3}
    const int r  = tid >> 3;    // row (0..31)
    ull acc0 = 0ULL, acc1 = 0ULL;

    #pragma unroll 6
    for (int j = 0; j < IN_DIM; j++) {
        double2 kd = *(const double2*)&kqt[j][sg * 4];
        float xv = xs[r][j];
        ull xd = fpack(xv, xv);
        acc0 = ffma2(d2u(kd.x), xd, acc0);
        acc1 = ffma2(d2u(kd.y), xd, acc1);
    }
    float2 d01 = funpack(acc0), d23 = funpack(acc1);
    float m = fmaxf(fmaxf(d01.x, d01.y), fmaxf(d23.x, d23.y));
    m = fmaxf(m, __shfl_xor_sync(0xffffffffu, m, 1));
    m = fmaxf(m, __shfl_xor_sync(0xffffffffu, m, 2));
    m = fmaxf(m, __shfl_xor_sync(0xffffffffu, m, 4));
    float e0 = __expf(d01.x - m), e1 = __expf(d01.y - m);
    float e2 = __expf(d23.x - m), e3 = __expf(d23.y - m);
    float sum = (e0 + e1) + (e2 + e3);
    sum += __shfl_xor_sync(0xffffffffu, sum, 1);
    sum += __shfl_xor_sync(0xffffffffu, sum, 2);
    sum += __shfl_xor_sync(0xffffffffu, sum, 4);
    float inv = 1.0f / sum;
    *(float4*)&w_out[(size_t)(row0 + r) * NS + sg * 4] =
        make_float4(e0 * inv, e1 * inv, e2 * inv, e3 * inv);
}

// ---------------------------------------------------------------------------
// C2: s_out[r][d] = sum_s w[r][s] * sl[b][s][d]   (K=32 skinny GEMM)
// ROUND-2 CONFIG (best measured: 80.2us).
// grid (6 d-tiles x 1024 row-tiles), 128 thr. Block tile 32 rows x 256 d.
// Warp = 8 rows x 256 d, lane owns distinct float4 pairs; w scalar splats.
// ---------------------------------------------------------------------------
__global__ __launch_bounds__(128, 4) void c2_kernel(const float* __restrict__ sl,
                                                    const float* __restrict__ w_in,
                                                    float* __restrict__ s_out) {
    const int d0   = blockIdx.x * 256;
    const int row0 = blockIdx.y * 32;
    const int b    = row0 >> 13;
    __shared__ float sls[NS][256];    // 32 KB
    __shared__ ull   wsp[32][NS];     // splatted w, 8 KB
    const int tid  = threadIdx.x;
    const int warp = tid >> 5, lane = tid & 31;
    const int rbase = warp * 8;

    #pragma unroll
    for (int t = 0; t < 16; t++) {    // 32 s x 256 d (float4)
        int idx = t * 128 + tid;
        int s = idx >> 6, dq = idx & 63;
        *(float4*)&sls[s][dq * 4] =
            *(const float4*)&sl[(size_t)(b * NS + s) * SD + d0 + dq * 4];
    }
    #pragma unroll
    for (int t = 0; t < 8; t++) {     // 32 rows x 32 s, splatted
        int idx = t * 128 + tid;
        int r = idx >> 5, s = idx & 31;
        float v = w_in[(size_t)(row0 + r) * NS + s];
        wsp[r][s] = fpack(v, v);
    }
    __syncthreads();

    ull acc[8][4];
    #pragma unroll
    for (int i = 0; i < 8; i++)
        #pragma unroll
        for (int q = 0; q < 4; q++) acc[i][q] = 0ULL;

    #pragma unroll 2
    for (int s = 0; s < NS; s++) {
        double2 a01 = *(const double2*)&sls[s][lane * 4];
        double2 a23 = *(const double2*)&sls[s][128 + lane * 4];
        ull A0 = d2u(a01.x), A1 = d2u(a01.y), A2 = d2u(a23.x), A3 = d2u(a23.y);
        #pragma unroll
        for (int i = 0; i < 8; i++) {
            ull wv = wsp[rbase + i][s];
            acc[i][0] = ffma2(A0, wv, acc[i][0]);
            acc[i][1] = ffma2(A1, wv, acc[i][1]);
            acc[i][2] = ffma2(A2, wv, acc[i][2]);
            acc[i][3] = ffma2(A3, wv, acc[i][3]);
        }
    }
    #pragma unroll
    for (int i = 0; i < 8; i++) {
        int r = row0 + rbase + i;
        float* dst = s_out + (size_t)r * SD + d0 + lane * 4;
        *(double2*)dst         = make_double2(u2d(acc[i][0]), u2d(acc[i][1]));
        *(double2*)(dst + 128) = make_double2(u2d(acc[i][2]), u2d(acc[i][3]));
    }
}

// ---------------------------------------------------------------------------
extern "C" void kernel_launch(void* const* d_in, const int* in_sizes, int n_in,
                              void* d_out, int out_size) {
    const float* x  = (const float*)d_in[0];   // [4,8192,180]
    const float* sl = (const float*)d_in[1];   // [4,32,1536]
    const float* Wq = (const float*)d_in[2];   // [180,1536]
    const float* Wk = (const float*)d_in[3];   // [1536,1536]
    float* out   = (float*)d_out;
    float* s_out = out;                               // [4,8192,1536]
    float* w_out = out + (size_t)NB * NR * SD;        // [4,8192,32]

    p1_kernel<<<dim3(AD / 256, BS / 32, KS), 128>>>(sl, Wk);
    p1r_kernel<<<(BS * AD / 4) / 256, 256>>>();
    p2_kernel<<<dim3(192 / JT, AC), 256>>>(Wq);
    c1_kernel<<<(NB * NR) / C1_ROWS, 256>>>(x, w_out);
    c2_kernel<<<dim3(SD / 256, (NB * NR) / 32), 128>>>(sl, w_out, s_out);
}

// round 9
// speedup vs baseline: 1.1778x; 1.0047x over previous
#include <cuda_runtime.h>

// ---------------------------------------------------------------------------
// MixingBlock: s = softmax((x Wq)(sl Wk)^T * scale) @ sl,  w = the softmax
// Restructure: dots = x @ KQ^T with KQ = scale * (sl Wk) Wq^T  (tiny [128,180])
// Pipeline: p1 -> p1r (reduce + zero KQT) -> p2 (atomic KQ) -> c1 -> c2
// ---------------------------------------------------------------------------

#define NB 4
#define NR 8192
#define NS 32
#define IN_DIM 180
#define SD 1536
#define AD 1536
#define BS (NB*NS)          // 128
#define KS 16               // d-split for p1
#define KCHUNK (SD/KS)      // 96
#define AC 24               // a-chunks for p2
#define ACHUNK (AD/AC)      // 64
#define JT 16               // j-tile for p2

typedef unsigned long long ull;

__device__ float g_kpart[KS][BS][AD];     // p1 partials
__device__ float g_kred[BS][AD];          // reduced k
__device__ float g_KQT[IN_DIM][BS];       // KQ transposed (scale folded in)

// ---- packed f32x2 helpers -------------------------------------------------
__device__ __forceinline__ ull fpack(float x, float y) {
    ull r; asm("mov.b64 %0, {%1, %2};" : "=l"(r) : "f"(x), "f"(y)); return r;
}
__device__ __forceinline__ float2 funpack(ull v) {
    float2 r; asm("mov.b64 {%0, %1}, %2;" : "=f"(r.x), "=f"(r.y) : "l"(v)); return r;
}
__device__ __forceinline__ ull ffma2(ull a, ull b, ull c) {
    ull d; asm("fma.rn.f32x2 %0, %1, %2, %3;" : "=l"(d) : "l"(a), "l"(b), "l"(c)); return d;
}
__device__ __forceinline__ ull d2u(double d) { return __double_as_longlong(d); }
__device__ __forceinline__ double u2d(ull v) { return __longlong_as_double(v); }

// ---------------------------------------------------------------------------
// P1: g_kpart[p][m][n] = sum_{d in chunk p} sl[m][d] * Wk[d][n]
// grid (6 n-tiles of 256, 4 m-tiles of 32, 16 d-chunks of 96), 128 thr.
// ---------------------------------------------------------------------------
__global__ __launch_bounds__(128) void p1_kernel(const float* __restrict__ sl,
                                                 const float* __restrict__ Wk) {
    const int n0 = blockIdx.x * 256;
    const int m0 = blockIdx.y * 32;
    const int p  = blockIdx.z;
    const int d0 = p * KCHUNK;
    __shared__ float sWk[16][256];
    __shared__ ull   sslp[16][33];
    const int tid  = threadIdx.x;
    const int warp = tid >> 5, lane = tid & 31;
    const int mbase = warp * 8;

    ull acc[8][4];
    #pragma unroll
    for (int i = 0; i < 8; i++)
        #pragma unroll
        for (int q = 0; q < 4; q++) acc[i][q] = 0ULL;

    for (int kk = 0; kk < KCHUNK; kk += 16) {
        __syncthreads();
        #pragma unroll
        for (int t = 0; t < 8; t++) {
            int idx = t * 128 + tid;
            int dd = idx >> 6, nq = idx & 63;
            *(float4*)&sWk[dd][nq * 4] =
                *(const float4*)&Wk[(size_t)(d0 + kk + dd) * AD + n0 + nq * 4];
        }
        #pragma unroll
        for (int t = 0; t < 4; t++) {
            int idx = t * 128 + tid;
            int m = idx >> 4, dd = idx & 15;
            float v = sl[(size_t)(m0 + m) * SD + d0 + kk + dd];
            sslp[dd][m] = fpack(v, v);
        }
        __syncthreads();
        #pragma unroll
        for (int dd = 0; dd < 16; dd++) {
            double2 a01 = *(const double2*)&sWk[dd][lane * 4];
            double2 a23 = *(const double2*)&sWk[dd][128 + lane * 4];
            ull A0 = d2u(a01.x), A1 = d2u(a01.y), A2 = d2u(a23.x), A3 = d2u(a23.y);
            #pragma unroll
            for (int i = 0; i < 8; i++) {
                ull wv = sslp[dd][mbase + i];
                acc[i][0] = ffma2(A0, wv, acc[i][0]);
                acc[i][1] = ffma2(A1, wv, acc[i][1]);
                acc[i][2] = ffma2(A2, wv, acc[i][2]);
                acc[i][3] = ffma2(A3, wv, acc[i][3]);
            }
        }
    }
    #pragma unroll
    for (int i = 0; i < 8; i++) {
        int m = m0 + mbase + i;
        float* dst = &g_kpart[p][m][n0 + lane * 4];
        *(double2*)dst         = make_double2(u2d(acc[i][0]), u2d(acc[i][1]));
        *(double2*)(dst + 128) = make_double2(u2d(acc[i][2]), u2d(acc[i][3]));
    }
}

// ---------------------------------------------------------------------------
// P1R: g_kred = sum_p g_kpart[p]; also zeros g_KQT for p2's atomics.
// ---------------------------------------------------------------------------
__global__ __launch_bounds__(256) void p1r_kernel() {
    int gid = blockIdx.x * 256 + threadIdx.x;    // over 128*1536/4 = 49152
    if (gid < IN_DIM * BS) (&g_KQT[0][0])[gid] = 0.f;
    const float4* src = (const float4*)&g_kpart[0][0][0];
    float4* dst = (float4*)&g_kred[0][0];
    const int stride = (BS * AD) / 4;
    float4 a = make_float4(0.f, 0.f, 0.f, 0.f);
    #pragma unroll
    for (int p = 0; p < KS; p++) {
        float4 v = src[(size_t)p * stride + gid];
        a.x += v.x; a.y += v.y; a.z += v.z; a.w += v.w;
    }
    dst[gid] = a;
}

// ---------------------------------------------------------------------------
// P2: g_KQT[j][m] += scale * sum_{a in chunk} kred[m][a] * Wq[j][a]
// grid (12 j-tiles of 16, 24 a-chunks of 64), 256 thr. RED.F32 accumulation.
// ---------------------------------------------------------------------------
__global__ __launch_bounds__(256) void p2_kernel(const float* __restrict__ Wq) {
    const int j0 = blockIdx.x * JT;
    const int ac = blockIdx.y;
    const int a0 = ac * ACHUNK;
    __shared__ float ksm[64][130];    // [a][m], padded
    __shared__ ull   wqs[64][18];     // splatted Wq [a][jj], padded
    const int tid = threadIdx.x;
    const int mp = tid & 63;          // m-pair: m = 2*mp
    const int jg = tid >> 6;          // j = j0 + jg*4 + {0..3}

    #pragma unroll
    for (int t = 0; t < 8; t++) {     // transpose kred chunk into ksm
        int idx = t * 256 + tid;
        int m = idx >> 4, aq = idx & 15;
        float4 v = *(const float4*)&g_kred[m][a0 + aq * 4];
        ksm[aq * 4 + 0][m] = v.x;
        ksm[aq * 4 + 1][m] = v.y;
        ksm[aq * 4 + 2][m] = v.z;
        ksm[aq * 4 + 3][m] = v.w;
    }
    const float scale = rsqrtf((float)AD);
    #pragma unroll
    for (int t = 0; t < 4; t++) {     // Wq splats
        int idx = t * 256 + tid;
        int jj = idx >> 6, a = idx & 63;
        int j = j0 + jj;
        float v = (j < IN_DIM) ? Wq[(size_t)j * AD + a0 + a] * scale : 0.f;
        wqs[a][jj] = fpack(v, v);
    }
    __syncthreads();

    ull acc[4] = {0ULL, 0ULL, 0ULL, 0ULL};
    #pragma unroll 4
    for (int a = 0; a < ACHUNK; a++) {
        ull kp = *(const ull*)&ksm[a][2 * mp];
        double2 w01 = *(const double2*)&wqs[a][jg * 4];
        double2 w23 = *(const double2*)&wqs[a][jg * 4 + 2];
        acc[0] = ffma2(kp, d2u(w01.x), acc[0]);
        acc[1] = ffma2(kp, d2u(w01.y), acc[1]);
        acc[2] = ffma2(kp, d2u(w23.x), acc[2]);
        acc[3] = ffma2(kp, d2u(w23.y), acc[3]);
    }
    #pragma unroll
    for (int q = 0; q < 4; q++) {
        int j = j0 + jg * 4 + q;
        if (j < IN_DIM) {
            float2 v = funpack(acc[q]);
            atomicAdd(&g_KQT[j][2 * mp], v.x);
            atomicAdd(&g_KQT[j][2 * mp + 1], v.y);
        }
    }
}

// ---------------------------------------------------------------------------
// C1: dots = x @ KQ^T (K=180), softmax over 32 slots, write w.
// grid 1024 (32 rows), 256 thr. Thread = 1 row x 4 slots.
// x consumed as float4 per 4 j (1 LDS.128 instead of 4 scalar LDS);
// launch_bounds(256,3) gives ptxas ~85 regs for load pipelining.
// ---------------------------------------------------------------------------
#define C1_ROWS 32
__global__ __launch_bounds__(256, 3) void c1_kernel(const float* __restrict__ x,
                                                    float* __restrict__ w_out) {
    const int row0 = blockIdx.x * C1_ROWS;
    const int b = row0 >> 13;
    __shared__ float xs[C1_ROWS][IN_DIM];     // 23 KB (rows 16-byte aligned: 180*4=720B)
    __shared__ float kqt[IN_DIM][32];         // 23 KB
    const int tid = threadIdx.x;

    for (int idx = tid; idx < C1_ROWS * 45; idx += 256) {
        int r = idx / 45, q = idx - r * 45;
        *(float4*)&xs[r][q * 4] =
            *(const float4*)&x[(size_t)(row0 + r) * IN_DIM + q * 4];
    }
    for (int idx = tid; idx < IN_DIM * NS; idx += 256) {
        int j = idx >> 5, s = idx & 31;
        kqt[j][s] = g_KQT[j][b * NS + s];
    }
    __syncthreads();

    const int sg = tid & 7;     // slots sg*4 + {0..3}
    const int r  = tid >> 3;    // row (0..31)
    ull acc0 = 0ULL, acc1 = 0ULL;

    #pragma unroll 3
    for (int j4 = 0; j4 < IN_DIM; j4 += 4) {
        float4 xv4 = *(const float4*)&xs[r][j4];
        #pragma unroll
        for (int t = 0; t < 4; t++) {
            double2 kd = *(const double2*)&kqt[j4 + t][sg * 4];
            float xv = (t == 0) ? xv4.x : (t == 1) ? xv4.y : (t == 2) ? xv4.z : xv4.w;
            ull xd = fpack(xv, xv);
            acc0 = ffma2(d2u(kd.x), xd, acc0);
            acc1 = ffma2(d2u(kd.y), xd, acc1);
        }
    }
    float2 d01 = funpack(acc0), d23 = funpack(acc1);
    float m = fmaxf(fmaxf(d01.x, d01.y), fmaxf(d23.x, d23.y));
    m = fmaxf(m, __shfl_xor_sync(0xffffffffu, m, 1));
    m = fmaxf(m, __shfl_xor_sync(0xffffffffu, m, 2));
    m = fmaxf(m, __shfl_xor_sync(0xffffffffu, m, 4));
    float e0 = __expf(d01.x - m), e1 = __expf(d01.y - m);
    float e2 = __expf(d23.x - m), e3 = __expf(d23.y - m);
    float sum = (e0 + e1) + (e2 + e3);
    sum += __shfl_xor_sync(0xffffffffu, sum, 1);
    sum += __shfl_xor_sync(0xffffffffu, sum, 2);
    sum += __shfl_xor_sync(0xffffffffu, sum, 4);
    float inv = 1.0f / sum;
    *(float4*)&w_out[(size_t)(row0 + r) * NS + sg * 4] =
        make_float4(e0 * inv, e1 * inv, e2 * inv, e3 * inv);
}

// ---------------------------------------------------------------------------
// C2: s_out[r][d] = sum_s w[r][s] * sl[b][s][d]   (K=32 skinny GEMM)
// ROUND-2 CONFIG (best measured: 80.2us) — unchanged.
// grid (6 d-tiles x 1024 row-tiles), 128 thr. Block tile 32 rows x 256 d.
// ---------------------------------------------------------------------------
__global__ __launch_bounds__(128, 4) void c2_kernel(const float* __restrict__ sl,
                                                    const float* __restrict__ w_in,
                                                    float* __restrict__ s_out) {
    const int d0   = blockIdx.x * 256;
    const int row0 = blockIdx.y * 32;
    const int b    = row0 >> 13;
    __shared__ float sls[NS][256];    // 32 KB
    __shared__ ull   wsp[32][NS];     // splatted w, 8 KB
    const int tid  = threadIdx.x;
    const int warp = tid >> 5, lane = tid & 31;
    const int rbase = warp * 8;

    #pragma unroll
    for (int t = 0; t < 16; t++) {    // 32 s x 256 d (float4)
        int idx = t * 128 + tid;
        int s = idx >> 6, dq = idx & 63;
        *(float4*)&sls[s][dq * 4] =
            *(const float4*)&sl[(size_t)(b * NS + s) * SD + d0 + dq * 4];
    }
    #pragma unroll
    for (int t = 0; t < 8; t++) {     // 32 rows x 32 s, splatted
        int idx = t * 128 + tid;
        int r = idx >> 5, s = idx & 31;
        float v = w_in[(size_t)(row0 + r) * NS + s];
        wsp[r][s] = fpack(v, v);
    }
    __syncthreads();

    ull acc[8][4];
    #pragma unroll
    for (int i = 0; i < 8; i++)
        #pragma unroll
        for (int q = 0; q < 4; q++) acc[i][q] = 0ULL;

    #pragma unroll 2
    for (int s = 0; s < NS; s++) {
        double2 a01 = *(const double2*)&sls[s][lane * 4];
        double2 a23 = *(const double2*)&sls[s][128 + lane * 4];
        ull A0 = d2u(a01.x), A1 = d2u(a01.y), A2 = d2u(a23.x), A3 = d2u(a23.y);
        #pragma unroll
        for (int i = 0; i < 8; i++) {
            ull wv = wsp[rbase + i][s];
            acc[i][0] = ffma2(A0, wv, acc[i][0]);
            acc[i][1] = ffma2(A1, wv, acc[i][1]);
            acc[i][2] = ffma2(A2, wv, acc[i][2]);
            acc[i][3] = ffma2(A3, wv, acc[i][3]);
        }
    }
    #pragma unroll
    for (int i = 0; i < 8; i++) {
        int r = row0 + rbase + i;
        float* dst = s_out + (size_t)r * SD + d0 + lane * 4;
        *(double2*)dst         = make_double2(u2d(acc[i][0]), u2d(acc[i][1]));
        *(double2*)(dst + 128) = make_double2(u2d(acc[i][2]), u2d(acc[i][3]));
    }
}

// ---------------------------------------------------------------------------
extern "C" void kernel_launch(void* const* d_in, const int* in_sizes, int n_in,
                              void* d_out, int out_size) {
    const float* x  = (const float*)d_in[0];   // [4,8192,180]
    const float* sl = (const float*)d_in[1];   // [4,32,1536]
    const float* Wq = (const float*)d_in[2];   // [180,1536]
    const float* Wk = (const float*)d_in[3];   // [1536,1536]
    float* out   = (float*)d_out;
    float* s_out = out;                               // [4,8192,1536]
    float* w_out = out + (size_t)NB * NR * SD;        // [4,8192,32]

    p1_kernel<<<dim3(AD / 256, BS / 32, KS), 128>>>(sl, Wk);
    p1r_kernel<<<(BS * AD / 4) / 256, 256>>>();
    p2_kernel<<<dim3(192 / JT, AC), 256>>>(Wq);
    c1_kernel<<<(NB * NR) / C1_ROWS, 256>>>(x, w_out);
    c2_kernel<<<dim3(SD / 256, (NB * NR) / 32), 128>>>(sl, w_out, s_out);
}

// round 10
// speedup vs baseline: 1.2583x; 1.0683x over previous
#include <cuda_runtime.h>
#include <cuda_bf16.h>

// ---------------------------------------------------------------------------
// MixingBlock: s = softmax((x Wq)(sl Wk)^T * scale) @ sl,  w = the softmax
// Restructure: dots = x @ KQ^T with KQ = scale * (sl Wk) Wq^T  (tiny [128,180])
// Pipeline: p1 -> p1r -> p2 (atomic KQ) -> c1 -> c2 (bf16-split tensor core)
// ---------------------------------------------------------------------------

#define NB 4
#define NR 8192
#define NS 32
#define IN_DIM 180
#define SD 1536
#define AD 1536
#define BS (NB*NS)          // 128
#define KS 16               // d-split for p1
#define KCHUNK (SD/KS)      // 96
#define AC 24               // a-chunks for p2
#define ACHUNK (AD/AC)      // 64
#define JT 16               // j-tile for p2

typedef unsigned long long ull;
typedef unsigned int u32;

__device__ float g_kpart[KS][BS][AD];     // p1 partials
__device__ float g_kred[BS][AD];          // reduced k
__device__ float g_KQT[IN_DIM][BS];       // KQ transposed (scale folded in)

// ---- packed f32x2 helpers -------------------------------------------------
__device__ __forceinline__ ull fpack(float x, float y) {
    ull r; asm("mov.b64 %0, {%1, %2};" : "=l"(r) : "f"(x), "f"(y)); return r;
}
__device__ __forceinline__ float2 funpack(ull v) {
    float2 r; asm("mov.b64 {%0, %1}, %2;" : "=f"(r.x), "=f"(r.y) : "l"(v)); return r;
}
__device__ __forceinline__ ull ffma2(ull a, ull b, ull c) {
    ull d; asm("fma.rn.f32x2 %0, %1, %2, %3;" : "=l"(d) : "l"(a), "l"(b), "l"(c)); return d;
}
__device__ __forceinline__ ull d2u(double d) { return __double_as_longlong(d); }
__device__ __forceinline__ double u2d(ull v) { return __longlong_as_double(v); }

// ---- bf16 helpers ---------------------------------------------------------
__device__ __forceinline__ u32 packbf2(float x, float y) {
    __nv_bfloat162 t = __floats2bfloat162_rn(x, y);   // x -> low, y -> high
    return *reinterpret_cast<u32*>(&t);
}
__device__ __forceinline__ float bf16rt(float v) {    // round-trip through bf16
    return __bfloat162float(__float2bfloat16_rn(v));
}
__device__ __forceinline__ void mma16816(float c[4], const u32 a[4], const u32 b[2]) {
    asm volatile(
        "mma.sync.aligned.m16n8k16.row.col.f32.bf16.bf16.f32 "
        "{%0,%1,%2,%3},{%4,%5,%6,%7},{%8,%9},{%0,%1,%2,%3};"
        : "+f"(c[0]), "+f"(c[1]), "+f"(c[2]), "+f"(c[3])
        : "r"(a[0]), "r"(a[1]), "r"(a[2]), "r"(a[3]), "r"(b[0]), "r"(b[1]));
}

// ---------------------------------------------------------------------------
// P1: g_kpart[p][m][n] = sum_{d in chunk p} sl[m][d] * Wk[d][n]
// grid (6 n-tiles of 256, 4 m-tiles of 32, 16 d-chunks of 96), 128 thr.
// ---------------------------------------------------------------------------
__global__ __launch_bounds__(128) void p1_kernel(const float* __restrict__ sl,
                                                 const float* __restrict__ Wk) {
    const int n0 = blockIdx.x * 256;
    const int m0 = blockIdx.y * 32;
    const int p  = blockIdx.z;
    const int d0 = p * KCHUNK;
    __shared__ float sWk[16][256];
    __shared__ ull   sslp[16][33];
    const int tid  = threadIdx.x;
    const int warp = tid >> 5, lane = tid & 31;
    const int mbase = warp * 8;

    ull acc[8][4];
    #pragma unroll
    for (int i = 0; i < 8; i++)
        #pragma unroll
        for (int q = 0; q < 4; q++) acc[i][q] = 0ULL;

    for (int kk = 0; kk < KCHUNK; kk += 16) {
        __syncthreads();
        #pragma unroll
        for (int t = 0; t < 8; t++) {
            int idx = t * 128 + tid;
            int dd = idx >> 6, nq = idx & 63;
            *(float4*)&sWk[dd][nq * 4] =
                *(const float4*)&Wk[(size_t)(d0 + kk + dd) * AD + n0 + nq * 4];
        }
        #pragma unroll
        for (int t = 0; t < 4; t++) {
            int idx = t * 128 + tid;
            int m = idx >> 4, dd = idx & 15;
            float v = sl[(size_t)(m0 + m) * SD + d0 + kk + dd];
            sslp[dd][m] = fpack(v, v);
        }
        __syncthreads();
        #pragma unroll
        for (int dd = 0; dd < 16; dd++) {
            double2 a01 = *(const double2*)&sWk[dd][lane * 4];
            double2 a23 = *(const double2*)&sWk[dd][128 + lane * 4];
            ull A0 = d2u(a01.x), A1 = d2u(a01.y), A2 = d2u(a23.x), A3 = d2u(a23.y);
            #pragma unroll
            for (int i = 0; i < 8; i++) {
                ull wv = sslp[dd][mbase + i];
                acc[i][0] = ffma2(A0, wv, acc[i][0]);
                acc[i][1] = ffma2(A1, wv, acc[i][1]);
                acc[i][2] = ffma2(A2, wv, acc[i][2]);
                acc[i][3] = ffma2(A3, wv, acc[i][3]);
            }
        }
    }
    #pragma unroll
    for (int i = 0; i < 8; i++) {
        int m = m0 + mbase + i;
        float* dst = &g_kpart[p][m][n0 + lane * 4];
        *(double2*)dst         = make_double2(u2d(acc[i][0]), u2d(acc[i][1]));
        *(double2*)(dst + 128) = make_double2(u2d(acc[i][2]), u2d(acc[i][3]));
    }
}

// ---------------------------------------------------------------------------
// P1R: g_kred = sum_p g_kpart[p]; also zeros g_KQT for p2's atomics.
// ---------------------------------------------------------------------------
__global__ __launch_bounds__(256) void p1r_kernel() {
    int gid = blockIdx.x * 256 + threadIdx.x;    // over 128*1536/4 = 49152
    if (gid < IN_DIM * BS) (&g_KQT[0][0])[gid] = 0.f;
    const float4* src = (const float4*)&g_kpart[0][0][0];
    float4* dst = (float4*)&g_kred[0][0];
    const int stride = (BS * AD) / 4;
    float4 a = make_float4(0.f, 0.f, 0.f, 0.f);
    #pragma unroll
    for (int p = 0; p < KS; p++) {
        float4 v = src[(size_t)p * stride + gid];
        a.x += v.x; a.y += v.y; a.z += v.z; a.w += v.w;
    }
    dst[gid] = a;
}

// ---------------------------------------------------------------------------
// P2: g_KQT[j][m] += scale * sum_{a in chunk} kred[m][a] * Wq[j][a]
// grid (12 j-tiles of 16, 24 a-chunks of 64), 256 thr. RED.F32 accumulation.
// ---------------------------------------------------------------------------
__global__ __launch_bounds__(256) void p2_kernel(const float* __restrict__ Wq) {
    const int j0 = blockIdx.x * JT;
    const int ac = blockIdx.y;
    const int a0 = ac * ACHUNK;
    __shared__ float ksm[64][130];    // [a][m], padded
    __shared__ ull   wqs[64][18];     // splatted Wq [a][jj], padded
    const int tid = threadIdx.x;
    const int mp = tid & 63;          // m-pair: m = 2*mp
    const int jg = tid >> 6;          // j = j0 + jg*4 + {0..3}

    #pragma unroll
    for (int t = 0; t < 8; t++) {     // transpose kred chunk into ksm
        int idx = t * 256 + tid;
        int m = idx >> 4, aq = idx & 15;
        float4 v = *(const float4*)&g_kred[m][a0 + aq * 4];
        ksm[aq * 4 + 0][m] = v.x;
        ksm[aq * 4 + 1][m] = v.y;
        ksm[aq * 4 + 2][m] = v.z;
        ksm[aq * 4 + 3][m] = v.w;
    }
    const float scale = rsqrtf((float)AD);
    #pragma unroll
    for (int t = 0; t < 4; t++) {     // Wq splats
        int idx = t * 256 + tid;
        int jj = idx >> 6, a = idx & 63;
        int j = j0 + jj;
        float v = (j < IN_DIM) ? Wq[(size_t)j * AD + a0 + a] * scale : 0.f;
        wqs[a][jj] = fpack(v, v);
    }
    __syncthreads();

    ull acc[4] = {0ULL, 0ULL, 0ULL, 0ULL};
    #pragma unroll 4
    for (int a = 0; a < ACHUNK; a++) {
        ull kp = *(const ull*)&ksm[a][2 * mp];
        double2 w01 = *(const double2*)&wqs[a][jg * 4];
        double2 w23 = *(const double2*)&wqs[a][jg * 4 + 2];
        acc[0] = ffma2(kp, d2u(w01.x), acc[0]);
        acc[1] = ffma2(kp, d2u(w01.y), acc[1]);
        acc[2] = ffma2(kp, d2u(w23.x), acc[2]);
        acc[3] = ffma2(kp, d2u(w23.y), acc[3]);
    }
    #pragma unroll
    for (int q = 0; q < 4; q++) {
        int j = j0 + jg * 4 + q;
        if (j < IN_DIM) {
            float2 v = funpack(acc[q]);
            atomicAdd(&g_KQT[j][2 * mp], v.x);
            atomicAdd(&g_KQT[j][2 * mp + 1], v.y);
        }
    }
}

// ---------------------------------------------------------------------------
// C1: dots = x @ KQ^T (K=180), softmax over 32 slots, write w.  (unchanged)
// ---------------------------------------------------------------------------
#define C1_ROWS 32
__global__ __launch_bounds__(256, 3) void c1_kernel(const float* __restrict__ x,
                                                    float* __restrict__ w_out) {
    const int row0 = blockIdx.x * C1_ROWS;
    const int b = row0 >> 13;
    __shared__ float xs[C1_ROWS][IN_DIM];
    __shared__ float kqt[IN_DIM][32];
    const int tid = threadIdx.x;

    for (int idx = tid; idx < C1_ROWS * 45; idx += 256) {
        int r = idx / 45, q = idx - r * 45;
        *(float4*)&xs[r][q * 4] =
            *(const float4*)&x[(size_t)(row0 + r) * IN_DIM + q * 4];
    }
    for (int idx = tid; idx < IN_DIM * NS; idx += 256) {
        int j = idx >> 5, s = idx & 31;
        kqt[j][s] = g_KQT[j][b * NS + s];
    }
    __syncthreads();

    const int sg = tid & 7;
    const int r  = tid >> 3;
    ull acc0 = 0ULL, acc1 = 0ULL;

    #pragma unroll 3
    for (int j4 = 0; j4 < IN_DIM; j4 += 4) {
        float4 xv4 = *(const float4*)&xs[r][j4];
        #pragma unroll
        for (int t = 0; t < 4; t++) {
            double2 kd = *(const double2*)&kqt[j4 + t][sg * 4];
            float xv = (t == 0) ? xv4.x : (t == 1) ? xv4.y : (t == 2) ? xv4.z : xv4.w;
            ull xd = fpack(xv, xv);
            acc0 = ffma2(d2u(kd.x), xd, acc0);
            acc1 = ffma2(d2u(kd.y), xd, acc1);
        }
    }
    float2 d01 = funpack(acc0), d23 = funpack(acc1);
    float m = fmaxf(fmaxf(d01.x, d01.y), fmaxf(d23.x, d23.y));
    m = fmaxf(m, __shfl_xor_sync(0xffffffffu, m, 1));
    m = fmaxf(m, __shfl_xor_sync(0xffffffffu, m, 2));
    m = fmaxf(m, __shfl_xor_sync(0xffffffffu, m, 4));
    float e0 = __expf(d01.x - m), e1 = __expf(d01.y - m);
    float e2 = __expf(d23.x - m), e3 = __expf(d23.y - m);
    float sum = (e0 + e1) + (e2 + e3);
    sum += __shfl_xor_sync(0xffffffffu, sum, 1);
    sum += __shfl_xor_sync(0xffffffffu, sum, 2);
    sum += __shfl_xor_sync(0xffffffffu, sum, 4);
    float inv = 1.0f / sum;
    *(float4*)&w_out[(size_t)(row0 + r) * NS + sg * 4] =
        make_float4(e0 * inv, e1 * inv, e2 * inv, e3 * inv);
}

// ---------------------------------------------------------------------------
// C2 (tensor core): s = w @ sl via mma.m16n8k16 bf16, 2-term hi/lo split.
// Error: drops only lo*lo (~2^-18 rel) + fp32 accum; ~1e-6 rel overall.
// Block = 64 rows x 128 d, 256 thr (8 warps), warp = 16r x 64d = 8 n-tiles.
// grid (12 d-tiles x 512 row-tiles).
// smem padded stride 20 -> conflict-free fragment loads.
// ---------------------------------------------------------------------------
__global__ __launch_bounds__(256, 3) void c2_kernel(const float* __restrict__ sl,
                                                    const float* __restrict__ w_in,
                                                    float* __restrict__ s_out) {
    const int d0   = blockIdx.x * 128;
    const int row0 = blockIdx.y * 64;
    const int b    = row0 >> 13;
    __shared__ u32 slT_hi[128][20];   // [d][s-pair] bf16x2, 10 KB
    __shared__ u32 slT_lo[128][20];   // 10 KB
    __shared__ u32 whi[64][20];       // [r][s-pair] bf16x2, 5 KB
    __shared__ u32 wlo[64][20];       // 5 KB
    const int tid = threadIdx.x;

    // ---- fill: sl split (16 s-pairs x 128 d) ----
    #pragma unroll
    for (int t = 0; t < 8; t++) {
        int idx = t * 256 + tid;
        int q = idx >> 7, d = idx & 127;          // s = 2q, 2q+1
        const float* base = &sl[(size_t)(b * NS + 2 * q) * SD + d0 + d];
        float v0 = base[0], v1 = base[SD];
        float h0 = bf16rt(v0), h1 = bf16rt(v1);
        slT_hi[d][q] = packbf2(h0, h1);
        slT_lo[d][q] = packbf2(v0 - h0, v1 - h1);
    }
    // ---- fill: w split (64 r x 16 s-pairs) ----
    #pragma unroll
    for (int t = 0; t < 4; t++) {
        int idx = t * 256 + tid;
        int r = idx >> 4, q = idx & 15;
        const float* wb = &w_in[(size_t)(row0 + r) * NS + 2 * q];
        float v0 = wb[0], v1 = wb[1];
        float h0 = bf16rt(v0), h1 = bf16rt(v1);
        whi[r][q] = packbf2(h0, h1);
        wlo[r][q] = packbf2(v0 - h0, v1 - h1);
    }
    __syncthreads();

    const int warp = tid >> 5, lane = tid & 31;
    const int gid = lane >> 2, tig = lane & 3;
    const int wr = (warp >> 1) * 16;    // 0,16,32,48
    const int wd = (warp & 1) * 64;     // 0,64

    // ---- A fragments (per warp, reused across all 8 n-tiles) ----
    u32 Ahi[8], Alo[8];
    #pragma unroll
    for (int k = 0; k < 2; k++) {
        int pb = k * 8;
        Ahi[k*4+0] = whi[wr + gid    ][pb + tig    ];
        Ahi[k*4+1] = whi[wr + gid + 8][pb + tig    ];
        Ahi[k*4+2] = whi[wr + gid    ][pb + tig + 4];
        Ahi[k*4+3] = whi[wr + gid + 8][pb + tig + 4];
        Alo[k*4+0] = wlo[wr + gid    ][pb + tig    ];
        Alo[k*4+1] = wlo[wr + gid + 8][pb + tig    ];
        Alo[k*4+2] = wlo[wr + gid    ][pb + tig + 4];
        Alo[k*4+3] = wlo[wr + gid + 8][pb + tig + 4];
    }

    #pragma unroll
    for (int nt = 0; nt < 8; nt++) {
        const int dcol = wd + nt * 8 + gid;       // B fragment column = n = d
        u32 Bh[4], Bl[4];                          // [kstep*2 + {b0,b1}]
        Bh[0] = slT_hi[dcol][tig];      Bh[1] = slT_hi[dcol][tig + 4];
        Bh[2] = slT_hi[dcol][8 + tig];  Bh[3] = slT_hi[dcol][12 + tig];
        Bl[0] = slT_lo[dcol][tig];      Bl[1] = slT_lo[dcol][tig + 4];
        Bl[2] = slT_lo[dcol][8 + tig];  Bl[3] = slT_lo[dcol][12 + tig];

        float c[4] = {0.f, 0.f, 0.f, 0.f};
        mma16816(c, &Ahi[0], &Bh[0]);   // hi*hi  k0-15
        mma16816(c, &Ahi[4], &Bh[2]);   // hi*hi  k16-31
        mma16816(c, &Ahi[0], &Bl[0]);   // hi*lo
        mma16816(c, &Ahi[4], &Bl[2]);
        mma16816(c, &Alo[0], &Bh[0]);   // lo*hi
        mma16816(c, &Alo[4], &Bh[2]);

        const int dg = d0 + wd + nt * 8 + tig * 2;
        *(float2*)&s_out[(size_t)(row0 + wr + gid    ) * SD + dg] = make_float2(c[0], c[1]);
        *(float2*)&s_out[(size_t)(row0 + wr + gid + 8) * SD + dg] = make_float2(c[2], c[3]);
    }
}

// ---------------------------------------------------------------------------
extern "C" void kernel_launch(void* const* d_in, const int* in_sizes, int n_in,
                              void* d_out, int out_size) {
    const float* x  = (const float*)d_in[0];   // [4,8192,180]
    const float* sl = (const float*)d_in[1];   // [4,32,1536]
    const float* Wq = (const float*)d_in[2];   // [180,1536]
    const float* Wk = (const float*)d_in[3];   // [1536,1536]
    float* out   = (float*)d_out;
    float* s_out = out;                               // [4,8192,1536]
    float* w_out = out + (size_t)NB * NR * SD;        // [4,8192,32]

    p1_kernel<<<dim3(AD / 256, BS / 32, KS), 128>>>(sl, Wk);
    p1r_kernel<<<(BS * AD / 4) / 256, 256>>>();
    p2_kernel<<<dim3(192 / JT, AC), 256>>>(Wq);
    c1_kernel<<<(NB * NR) / C1_ROWS, 256>>>(x, w_out);
    c2_kernel<<<dim3(SD / 128, (NB * NR) / 64), 256>>>(sl, w_out, s_out);
}

// round 11
// speedup vs baseline: 1.4072x; 1.1184x over previous
#include <cuda_runtime.h>
#include <cuda_bf16.h>

// ---------------------------------------------------------------------------
// MixingBlock: s = softmax((x Wq)(sl Wk)^T * scale) @ sl,  w = the softmax
// Restructure: dots = x @ KQ^T with KQ = scale * (sl Wk) Wq^T  (tiny [128,180])
// Pipeline: p1 -> p1r -> p2 (atomic KQ) -> c1 (bf16 mma) -> c2 (bf16 mma)
// ---------------------------------------------------------------------------

#define NB 4
#define NR 8192
#define NS 32
#define IN_DIM 180
#define SD 1536
#define AD 1536
#define BS (NB*NS)          // 128
#define KS 16               // d-split for p1
#define KCHUNK (SD/KS)      // 96
#define AC 24               // a-chunks for p2
#define ACHUNK (AD/AC)      // 64
#define JT 16               // j-tile for p2

typedef unsigned long long ull;
typedef unsigned int u32;

__device__ float g_kpart[KS][BS][AD];     // p1 partials
__device__ float g_kred[BS][AD];          // reduced k
__device__ float g_KQT[IN_DIM][BS];       // KQ transposed (scale folded in)

// ---- packed f32x2 helpers -------------------------------------------------
__device__ __forceinline__ ull fpack(float x, float y) {
    ull r; asm("mov.b64 %0, {%1, %2};" : "=l"(r) : "f"(x), "f"(y)); return r;
}
__device__ __forceinline__ float2 funpack(ull v) {
    float2 r; asm("mov.b64 {%0, %1}, %2;" : "=f"(r.x), "=f"(r.y) : "l"(v)); return r;
}
__device__ __forceinline__ ull ffma2(ull a, ull b, ull c) {
    ull d; asm("fma.rn.f32x2 %0, %1, %2, %3;" : "=l"(d) : "l"(a), "l"(b), "l"(c)); return d;
}
__device__ __forceinline__ ull d2u(double d) { return __double_as_longlong(d); }
__device__ __forceinline__ double u2d(ull v) { return __longlong_as_double(v); }

// ---- bf16 helpers ---------------------------------------------------------
__device__ __forceinline__ u32 packbf2(float x, float y) {
    __nv_bfloat162 t = __floats2bfloat162_rn(x, y);   // x -> low, y -> high
    return *reinterpret_cast<u32*>(&t);
}
__device__ __forceinline__ float bf16rt(float v) {
    return __bfloat162float(__float2bfloat16_rn(v));
}
__device__ __forceinline__ void mma16816(float c[4], const u32 a[4], const u32 b[2]) {
    asm volatile(
        "mma.sync.aligned.m16n8k16.row.col.f32.bf16.bf16.f32 "
        "{%0,%1,%2,%3},{%4,%5,%6,%7},{%8,%9},{%0,%1,%2,%3};"
        : "+f"(c[0]), "+f"(c[1]), "+f"(c[2]), "+f"(c[3])
        : "r"(a[0]), "r"(a[1]), "r"(a[2]), "r"(a[3]), "r"(b[0]), "r"(b[1]));
}

// ---------------------------------------------------------------------------
// P1: g_kpart[p][m][n] = sum_{d in chunk p} sl[m][d] * Wk[d][n]
// ---------------------------------------------------------------------------
__global__ __launch_bounds__(128) void p1_kernel(const float* __restrict__ sl,
                                                 const float* __restrict__ Wk) {
    const int n0 = blockIdx.x * 256;
    const int m0 = blockIdx.y * 32;
    const int p  = blockIdx.z;
    const int d0 = p * KCHUNK;
    __shared__ float sWk[16][256];
    __shared__ ull   sslp[16][33];
    const int tid  = threadIdx.x;
    const int warp = tid >> 5, lane = tid & 31;
    const int mbase = warp * 8;

    ull acc[8][4];
    #pragma unroll
    for (int i = 0; i < 8; i++)
        #pragma unroll
        for (int q = 0; q < 4; q++) acc[i][q] = 0ULL;

    for (int kk = 0; kk < KCHUNK; kk += 16) {
        __syncthreads();
        #pragma unroll
        for (int t = 0; t < 8; t++) {
            int idx = t * 128 + tid;
            int dd = idx >> 6, nq = idx & 63;
            *(float4*)&sWk[dd][nq * 4] =
                *(const float4*)&Wk[(size_t)(d0 + kk + dd) * AD + n0 + nq * 4];
        }
        #pragma unroll
        for (int t = 0; t < 4; t++) {
            int idx = t * 128 + tid;
            int m = idx >> 4, dd = idx & 15;
            float v = sl[(size_t)(m0 + m) * SD + d0 + kk + dd];
            sslp[dd][m] = fpack(v, v);
        }
        __syncthreads();
        #pragma unroll
        for (int dd = 0; dd < 16; dd++) {
            double2 a01 = *(const double2*)&sWk[dd][lane * 4];
            double2 a23 = *(const double2*)&sWk[dd][128 + lane * 4];
            ull A0 = d2u(a01.x), A1 = d2u(a01.y), A2 = d2u(a23.x), A3 = d2u(a23.y);
            #pragma unroll
            for (int i = 0; i < 8; i++) {
                ull wv = sslp[dd][mbase + i];
                acc[i][0] = ffma2(A0, wv, acc[i][0]);
                acc[i][1] = ffma2(A1, wv, acc[i][1]);
                acc[i][2] = ffma2(A2, wv, acc[i][2]);
                acc[i][3] = ffma2(A3, wv, acc[i][3]);
            }
        }
    }
    #pragma unroll
    for (int i = 0; i < 8; i++) {
        int m = m0 + mbase + i;
        float* dst = &g_kpart[p][m][n0 + lane * 4];
        *(double2*)dst         = make_double2(u2d(acc[i][0]), u2d(acc[i][1]));
        *(double2*)(dst + 128) = make_double2(u2d(acc[i][2]), u2d(acc[i][3]));
    }
}

// ---------------------------------------------------------------------------
// P1R: g_kred = sum_p g_kpart[p]; also zeros g_KQT for p2's atomics.
// ---------------------------------------------------------------------------
__global__ __launch_bounds__(256) void p1r_kernel() {
    int gid = blockIdx.x * 256 + threadIdx.x;
    if (gid < IN_DIM * BS) (&g_KQT[0][0])[gid] = 0.f;
    const float4* src = (const float4*)&g_kpart[0][0][0];
    float4* dst = (float4*)&g_kred[0][0];
    const int stride = (BS * AD) / 4;
    float4 a = make_float4(0.f, 0.f, 0.f, 0.f);
    #pragma unroll
    for (int p = 0; p < KS; p++) {
        float4 v = src[(size_t)p * stride + gid];
        a.x += v.x; a.y += v.y; a.z += v.z; a.w += v.w;
    }
    dst[gid] = a;
}

// ---------------------------------------------------------------------------
// P2: g_KQT[j][m] += scale * sum_{a in chunk} kred[m][a] * Wq[j][a]
// ---------------------------------------------------------------------------
__global__ __launch_bounds__(256) void p2_kernel(const float* __restrict__ Wq) {
    const int j0 = blockIdx.x * JT;
    const int ac = blockIdx.y;
    const int a0 = ac * ACHUNK;
    __shared__ float ksm[64][130];
    __shared__ ull   wqs[64][18];
    const int tid = threadIdx.x;
    const int mp = tid & 63;
    const int jg = tid >> 6;

    #pragma unroll
    for (int t = 0; t < 8; t++) {
        int idx = t * 256 + tid;
        int m = idx >> 4, aq = idx & 15;
        float4 v = *(const float4*)&g_kred[m][a0 + aq * 4];
        ksm[aq * 4 + 0][m] = v.x;
        ksm[aq * 4 + 1][m] = v.y;
        ksm[aq * 4 + 2][m] = v.z;
        ksm[aq * 4 + 3][m] = v.w;
    }
    const float scale = rsqrtf((float)AD);
    #pragma unroll
    for (int t = 0; t < 4; t++) {
        int idx = t * 256 + tid;
        int jj = idx >> 6, a = idx & 63;
        int j = j0 + jj;
        float v = (j < IN_DIM) ? Wq[(size_t)j * AD + a0 + a] * scale : 0.f;
        wqs[a][jj] = fpack(v, v);
    }
    __syncthreads();

    ull acc[4] = {0ULL, 0ULL, 0ULL, 0ULL};
    #pragma unroll 4
    for (int a = 0; a < ACHUNK; a++) {
        ull kp = *(const ull*)&ksm[a][2 * mp];
        double2 w01 = *(const double2*)&wqs[a][jg * 4];
        double2 w23 = *(const double2*)&wqs[a][jg * 4 + 2];
        acc[0] = ffma2(kp, d2u(w01.x), acc[0]);
        acc[1] = ffma2(kp, d2u(w01.y), acc[1]);
        acc[2] = ffma2(kp, d2u(w23.x), acc[2]);
        acc[3] = ffma2(kp, d2u(w23.y), acc[3]);
    }
    #pragma unroll
    for (int q = 0; q < 4; q++) {
        int j = j0 + jg * 4 + q;
        if (j < IN_DIM) {
            float2 v = funpack(acc[q]);
            atomicAdd(&g_KQT[j][2 * mp], v.x);
            atomicAdd(&g_KQT[j][2 * mp + 1], v.y);
        }
    }
}

// ---------------------------------------------------------------------------
// C1 (tensor core): dots = x @ KQ (M=32768, N=32, K=180 pad 192) via
// mma.m16n8k16 bf16 3-term split, then softmax over 32 slots, write w.
// Block = 64 rows, 128 thr (4 warps), warp = 16 rows x 32 slots.
// Dynamic smem: xhi/xlo [64][100], khi/klo [32][100] = 76.8 KB, 2 blk/SM.
// ---------------------------------------------------------------------------
#define C1_SMEM 76800
__global__ __launch_bounds__(128, 2) void c1_kernel(const float* __restrict__ x,
                                                    float* __restrict__ w_out) {
    extern __shared__ u32 c1sm[];
    u32* xhi = c1sm;                 // [64][100]
    u32* xlo = c1sm + 6400;          // [64][100]
    u32* khi = c1sm + 12800;         // [32][100]
    u32* klo = c1sm + 16000;         // [32][100]

    const int row0 = blockIdx.x * 64;
    const int b = row0 >> 13;
    const int tid = threadIdx.x;

    // fill x: 64 rows x 45 float4 (= 90 bf16x2 pairs per row)
    for (int idx = tid; idx < 64 * 45; idx += 128) {
        int r = idx / 45, q = idx - r * 45;
        float4 v = *(const float4*)&x[(size_t)(row0 + r) * IN_DIM + q * 4];
        float h0 = bf16rt(v.x), h1 = bf16rt(v.y);
        float h2 = bf16rt(v.z), h3 = bf16rt(v.w);
        xhi[r * 100 + 2 * q]     = packbf2(h0, h1);
        xhi[r * 100 + 2 * q + 1] = packbf2(h2, h3);
        xlo[r * 100 + 2 * q]     = packbf2(v.x - h0, v.y - h1);
        xlo[r * 100 + 2 * q + 1] = packbf2(v.z - h2, v.w - h3);
    }
    // zero pad pairs 90..95
    for (int idx = tid; idx < 64 * 6; idx += 128) {
        int r = idx / 6, jp = 90 + idx - (idx / 6) * 6;
        xhi[r * 100 + jp] = 0u;
        xlo[r * 100 + jp] = 0u;
    }
    // fill KQ: [s][jp] from g_KQT[j][b*32+s]
    for (int idx = tid; idx < NS * 96; idx += 128) {
        int s = idx & 31, jp = idx >> 5;
        float f0 = (2 * jp     < IN_DIM) ? g_KQT[2 * jp][b * NS + s]     : 0.f;
        float f1 = (2 * jp + 1 < IN_DIM) ? g_KQT[2 * jp + 1][b * NS + s] : 0.f;
        float h0 = bf16rt(f0), h1 = bf16rt(f1);
        khi[s * 100 + jp] = packbf2(h0, h1);
        klo[s * 100 + jp] = packbf2(f0 - h0, f1 - h1);
    }
    __syncthreads();

    const int warp = tid >> 5, lane = tid & 31;
    const int gid = lane >> 2, tig = lane & 3;
    const int wr = warp * 16;

    float c[4][4];
    #pragma unroll
    for (int nt = 0; nt < 4; nt++)
        #pragma unroll
        for (int q = 0; q < 4; q++) c[nt][q] = 0.f;

    #pragma unroll
    for (int kt = 0; kt < 12; kt++) {
        const int pb = kt * 8;
        u32 Ah[4], Al[4];
        Ah[0] = xhi[(wr + gid    ) * 100 + pb + tig];
        Ah[1] = xhi[(wr + gid + 8) * 100 + pb + tig];
        Ah[2] = xhi[(wr + gid    ) * 100 + pb + tig + 4];
        Ah[3] = xhi[(wr + gid + 8) * 100 + pb + tig + 4];
        Al[0] = xlo[(wr + gid    ) * 100 + pb + tig];
        Al[1] = xlo[(wr + gid + 8) * 100 + pb + tig];
        Al[2] = xlo[(wr + gid    ) * 100 + pb + tig + 4];
        Al[3] = xlo[(wr + gid + 8) * 100 + pb + tig + 4];
        #pragma unroll
        for (int nt = 0; nt < 4; nt++) {
            const int n = nt * 8 + gid;
            u32 Bh[2] = { khi[n * 100 + pb + tig], khi[n * 100 + pb + tig + 4] };
            u32 Bl[2] = { klo[n * 100 + pb + tig], klo[n * 100 + pb + tig + 4] };
            mma16816(c[nt], Ah, Bh);
            mma16816(c[nt], Ah, Bl);
            mma16816(c[nt], Al, Bh);
        }
    }

    // softmax: rows wr+gid (c[nt][0..1]) and wr+gid+8 (c[nt][2..3]);
    // each row's 32 dots live in this lane-quad (xor 1,2).
    float m0 = -1e30f, m1 = -1e30f;
    #pragma unroll
    for (int nt = 0; nt < 4; nt++) {
        m0 = fmaxf(m0, fmaxf(c[nt][0], c[nt][1]));
        m1 = fmaxf(m1, fmaxf(c[nt][2], c[nt][3]));
    }
    m0 = fmaxf(m0, __shfl_xor_sync(0xffffffffu, m0, 1));
    m0 = fmaxf(m0, __shfl_xor_sync(0xffffffffu, m0, 2));
    m1 = fmaxf(m1, __shfl_xor_sync(0xffffffffu, m1, 1));
    m1 = fmaxf(m1, __shfl_xor_sync(0xffffffffu, m1, 2));

    float e[4][4];
    float s0 = 0.f, s1 = 0.f;
    #pragma unroll
    for (int nt = 0; nt < 4; nt++) {
        e[nt][0] = __expf(c[nt][0] - m0);
        e[nt][1] = __expf(c[nt][1] - m0);
        e[nt][2] = __expf(c[nt][2] - m1);
        e[nt][3] = __expf(c[nt][3] - m1);
        s0 += e[nt][0] + e[nt][1];
        s1 += e[nt][2] + e[nt][3];
    }
    s0 += __shfl_xor_sync(0xffffffffu, s0, 1);
    s0 += __shfl_xor_sync(0xffffffffu, s0, 2);
    s1 += __shfl_xor_sync(0xffffffffu, s1, 1);
    s1 += __shfl_xor_sync(0xffffffffu, s1, 2);
    float i0 = 1.0f / s0, i1 = 1.0f / s1;

    #pragma unroll
    for (int nt = 0; nt < 4; nt++) {
        const int n = nt * 8 + tig * 2;
        *(float2*)&w_out[(size_t)(row0 + wr + gid    ) * NS + n] =
            make_float2(e[nt][0] * i0, e[nt][1] * i0);
        *(float2*)&w_out[(size_t)(row0 + wr + gid + 8) * NS + n] =
            make_float2(e[nt][2] * i1, e[nt][3] * i1);
    }
}

// ---------------------------------------------------------------------------
// C2 (tensor core): s = w @ sl via mma.m16n8k16 bf16 3-term split. (unchanged)
// ---------------------------------------------------------------------------
__global__ __launch_bounds__(256, 3) void c2_kernel(const float* __restrict__ sl,
                                                    const float* __restrict__ w_in,
                                                    float* __restrict__ s_out) {
    const int d0   = blockIdx.x * 128;
    const int row0 = blockIdx.y * 64;
    const int b    = row0 >> 13;
    __shared__ u32 slT_hi[128][20];
    __shared__ u32 slT_lo[128][20];
    __shared__ u32 whi[64][20];
    __shared__ u32 wlo[64][20];
    const int tid = threadIdx.x;

    #pragma unroll
    for (int t = 0; t < 8; t++) {
        int idx = t * 256 + tid;
        int q = idx >> 7, d = idx & 127;
        const float* base = &sl[(size_t)(b * NS + 2 * q) * SD + d0 + d];
        float v0 = base[0], v1 = base[SD];
        float h0 = bf16rt(v0), h1 = bf16rt(v1);
        slT_hi[d][q] = packbf2(h0, h1);
        slT_lo[d][q] = packbf2(v0 - h0, v1 - h1);
    }
    #pragma unroll
    for (int t = 0; t < 4; t++) {
        int idx = t * 256 + tid;
        int r = idx >> 4, q = idx & 15;
        const float* wb = &w_in[(size_t)(row0 + r) * NS + 2 * q];
        float v0 = wb[0], v1 = wb[1];
        float h0 = bf16rt(v0), h1 = bf16rt(v1);
        whi[r][q] = packbf2(h0, h1);
        wlo[r][q] = packbf2(v0 - h0, v1 - h1);
    }
    __syncthreads();

    const int warp = tid >> 5, lane = tid & 31;
    const int gid = lane >> 2, tig = lane & 3;
    const int wr = (warp >> 1) * 16;
    const int wd = (warp & 1) * 64;

    u32 Ahi[8], Alo[8];
    #pragma unroll
    for (int k = 0; k < 2; k++) {
        int pb = k * 8;
        Ahi[k*4+0] = whi[wr + gid    ][pb + tig    ];
        Ahi[k*4+1] = whi[wr + gid + 8][pb + tig    ];
        Ahi[k*4+2] = whi[wr + gid    ][pb + tig + 4];
        Ahi[k*4+3] = whi[wr + gid + 8][pb + tig + 4];
        Alo[k*4+0] = wlo[wr + gid    ][pb + tig    ];
        Alo[k*4+1] = wlo[wr + gid + 8][pb + tig    ];
        Alo[k*4+2] = wlo[wr + gid    ][pb + tig + 4];
        Alo[k*4+3] = wlo[wr + gid + 8][pb + tig + 4];
    }

    #pragma unroll
    for (int nt = 0; nt < 8; nt++) {
        const int dcol = wd + nt * 8 + gid;
        u32 Bh[4], Bl[4];
        Bh[0] = slT_hi[dcol][tig];      Bh[1] = slT_hi[dcol][tig + 4];
        Bh[2] = slT_hi[dcol][8 + tig];  Bh[3] = slT_hi[dcol][12 + tig];
        Bl[0] = slT_lo[dcol][tig];      Bl[1] = slT_lo[dcol][tig + 4];
        Bl[2] = slT_lo[dcol][8 + tig];  Bl[3] = slT_lo[dcol][12 + tig];

        float c[4] = {0.f, 0.f, 0.f, 0.f};
        mma16816(c, &Ahi[0], &Bh[0]);
        mma16816(c, &Ahi[4], &Bh[2]);
        mma16816(c, &Ahi[0], &Bl[0]);
        mma16816(c, &Ahi[4], &Bl[2]);
        mma16816(c, &Alo[0], &Bh[0]);
        mma16816(c, &Alo[4], &Bh[2]);

        const int dg = d0 + wd + nt * 8 + tig * 2;
        *(float2*)&s_out[(size_t)(row0 + wr + gid    ) * SD + dg] = make_float2(c[0], c[1]);
        *(float2*)&s_out[(size_t)(row0 + wr + gid + 8) * SD + dg] = make_float2(c[2], c[3]);
    }
}

// ---------------------------------------------------------------------------
extern "C" void kernel_launch(void* const* d_in, const int* in_sizes, int n_in,
                              void* d_out, int out_size) {
    const float* x  = (const float*)d_in[0];   // [4,8192,180]
    const float* sl = (const float*)d_in[1];   // [4,32,1536]
    const float* Wq = (const float*)d_in[2];   // [180,1536]
    const float* Wk = (const float*)d_in[3];   // [1536,1536]
    float* out   = (float*)d_out;
    float* s_out = out;                               // [4,8192,1536]
    float* w_out = out + (size_t)NB * NR * SD;        // [4,8192,32]

    static int attr_done = 0;
    if (!attr_done) {
        cudaFuncSetAttribute(c1_kernel,
                             cudaFuncAttributeMaxDynamicSharedMemorySize, C1_SMEM);
        attr_done = 1;
    }

    p1_kernel<<<dim3(AD / 256, BS / 32, KS), 128>>>(sl, Wk);
    p1r_kernel<<<(BS * AD / 4) / 256, 256>>>();
    p2_kernel<<<dim3(192 / JT, AC), 256>>>(Wq);
    c1_kernel<<<(NB * NR) / 64, 128, C1_SMEM>>>(x, w_out);
    c2_kernel<<<dim3(SD / 128, (NB * NR) / 64), 256>>>(sl, w_out, s_out);
}

// round 12
// speedup vs baseline: 1.4280x; 1.0148x over previous
#include <cuda_runtime.h>
#include <cuda_bf16.h>

// ---------------------------------------------------------------------------
// MixingBlock: s = softmax((x Wq)(sl Wk)^T * scale) @ sl,  w = the softmax
// Restructure: dots = x @ KQ^T with KQ = scale * (sl Wk) Wq^T  (tiny [128,180])
// Pipeline: p1 -> p1r -> p2 (atomic KQ) -> c1 (bf16 mma) -> c2 (bf16 mma,
//           smem-staged coalesced stores)
// ---------------------------------------------------------------------------

#define NB 4
#define NR 8192
#define NS 32
#define IN_DIM 180
#define SD 1536
#define AD 1536
#define BS (NB*NS)          // 128
#define KS 16               // d-split for p1
#define KCHUNK (SD/KS)      // 96
#define AC 24               // a-chunks for p2
#define ACHUNK (AD/AC)      // 64
#define JT 16               // j-tile for p2

typedef unsigned long long ull;
typedef unsigned int u32;

__device__ float g_kpart[KS][BS][AD];     // p1 partials
__device__ float g_kred[BS][AD];          // reduced k
__device__ float g_KQT[IN_DIM][BS];       // KQ transposed (scale folded in)

// ---- packed f32x2 helpers -------------------------------------------------
__device__ __forceinline__ ull fpack(float x, float y) {
    ull r; asm("mov.b64 %0, {%1, %2};" : "=l"(r) : "f"(x), "f"(y)); return r;
}
__device__ __forceinline__ float2 funpack(ull v) {
    float2 r; asm("mov.b64 {%0, %1}, %2;" : "=f"(r.x), "=f"(r.y) : "l"(v)); return r;
}
__device__ __forceinline__ ull ffma2(ull a, ull b, ull c) {
    ull d; asm("fma.rn.f32x2 %0, %1, %2, %3;" : "=l"(d) : "l"(a), "l"(b), "l"(c)); return d;
}
__device__ __forceinline__ ull d2u(double d) { return __double_as_longlong(d); }
__device__ __forceinline__ double u2d(ull v) { return __longlong_as_double(v); }

// ---- bf16 helpers ---------------------------------------------------------
__device__ __forceinline__ u32 packbf2(float x, float y) {
    __nv_bfloat162 t = __floats2bfloat162_rn(x, y);   // x -> low, y -> high
    return *reinterpret_cast<u32*>(&t);
}
__device__ __forceinline__ float bf16rt(float v) {
    return __bfloat162float(__float2bfloat16_rn(v));
}
__device__ __forceinline__ void mma16816(float c[4], const u32 a[4], const u32 b[2]) {
    asm volatile(
        "mma.sync.aligned.m16n8k16.row.col.f32.bf16.bf16.f32 "
        "{%0,%1,%2,%3},{%4,%5,%6,%7},{%8,%9},{%0,%1,%2,%3};"
        : "+f"(c[0]), "+f"(c[1]), "+f"(c[2]), "+f"(c[3])
        : "r"(a[0]), "r"(a[1]), "r"(a[2]), "r"(a[3]), "r"(b[0]), "r"(b[1]));
}

// ---------------------------------------------------------------------------
// P1: g_kpart[p][m][n] = sum_{d in chunk p} sl[m][d] * Wk[d][n]
// ---------------------------------------------------------------------------
__global__ __launch_bounds__(128) void p1_kernel(const float* __restrict__ sl,
                                                 const float* __restrict__ Wk) {
    const int n0 = blockIdx.x * 256;
    const int m0 = blockIdx.y * 32;
    const int p  = blockIdx.z;
    const int d0 = p * KCHUNK;
    __shared__ float sWk[16][256];
    __shared__ ull   sslp[16][33];
    const int tid  = threadIdx.x;
    const int warp = tid >> 5, lane = tid & 31;
    const int mbase = warp * 8;

    ull acc[8][4];
    #pragma unroll
    for (int i = 0; i < 8; i++)
        #pragma unroll
        for (int q = 0; q < 4; q++) acc[i][q] = 0ULL;

    for (int kk = 0; kk < KCHUNK; kk += 16) {
        __syncthreads();
        #pragma unroll
        for (int t = 0; t < 8; t++) {
            int idx = t * 128 + tid;
            int dd = idx >> 6, nq = idx & 63;
            *(float4*)&sWk[dd][nq * 4] =
                *(const float4*)&Wk[(size_t)(d0 + kk + dd) * AD + n0 + nq * 4];
        }
        #pragma unroll
        for (int t = 0; t < 4; t++) {
            int idx = t * 128 + tid;
            int m = idx >> 4, dd = idx & 15;
            float v = sl[(size_t)(m0 + m) * SD + d0 + kk + dd];
            sslp[dd][m] = fpack(v, v);
        }
        __syncthreads();
        #pragma unroll
        for (int dd = 0; dd < 16; dd++) {
            double2 a01 = *(const double2*)&sWk[dd][lane * 4];
            double2 a23 = *(const double2*)&sWk[dd][128 + lane * 4];
            ull A0 = d2u(a01.x), A1 = d2u(a01.y), A2 = d2u(a23.x), A3 = d2u(a23.y);
            #pragma unroll
            for (int i = 0; i < 8; i++) {
                ull wv = sslp[dd][mbase + i];
                acc[i][0] = ffma2(A0, wv, acc[i][0]);
                acc[i][1] = ffma2(A1, wv, acc[i][1]);
                acc[i][2] = ffma2(A2, wv, acc[i][2]);
                acc[i][3] = ffma2(A3, wv, acc[i][3]);
            }
        }
    }
    #pragma unroll
    for (int i = 0; i < 8; i++) {
        int m = m0 + mbase + i;
        float* dst = &g_kpart[p][m][n0 + lane * 4];
        *(double2*)dst         = make_double2(u2d(acc[i][0]), u2d(acc[i][1]));
        *(double2*)(dst + 128) = make_double2(u2d(acc[i][2]), u2d(acc[i][3]));
    }
}

// ---------------------------------------------------------------------------
// P1R: g_kred = sum_p g_kpart[p]; also zeros g_KQT for p2's atomics.
// ---------------------------------------------------------------------------
__global__ __launch_bounds__(256) void p1r_kernel() {
    int gid = blockIdx.x * 256 + threadIdx.x;
    if (gid < IN_DIM * BS) (&g_KQT[0][0])[gid] = 0.f;
    const float4* src = (const float4*)&g_kpart[0][0][0];
    float4* dst = (float4*)&g_kred[0][0];
    const int stride = (BS * AD) / 4;
    float4 a = make_float4(0.f, 0.f, 0.f, 0.f);
    #pragma unroll
    for (int p = 0; p < KS; p++) {
        float4 v = src[(size_t)p * stride + gid];
        a.x += v.x; a.y += v.y; a.z += v.z; a.w += v.w;
    }
    dst[gid] = a;
}

// ---------------------------------------------------------------------------
// P2: g_KQT[j][m] += scale * sum_{a in chunk} kred[m][a] * Wq[j][a]
// ---------------------------------------------------------------------------
__global__ __launch_bounds__(256) void p2_kernel(const float* __restrict__ Wq) {
    const int j0 = blockIdx.x * JT;
    const int ac = blockIdx.y;
    const int a0 = ac * ACHUNK;
    __shared__ float ksm[64][130];
    __shared__ ull   wqs[64][18];
    const int tid = threadIdx.x;
    const int mp = tid & 63;
    const int jg = tid >> 6;

    #pragma unroll
    for (int t = 0; t < 8; t++) {
        int idx = t * 256 + tid;
        int m = idx >> 4, aq = idx & 15;
        float4 v = *(const float4*)&g_kred[m][a0 + aq * 4];
        ksm[aq * 4 + 0][m] = v.x;
        ksm[aq * 4 + 1][m] = v.y;
        ksm[aq * 4 + 2][m] = v.z;
        ksm[aq * 4 + 3][m] = v.w;
    }
    const float scale = rsqrtf((float)AD);
    #pragma unroll
    for (int t = 0; t < 4; t++) {
        int idx = t * 256 + tid;
        int jj = idx >> 6, a = idx & 63;
        int j = j0 + jj;
        float v = (j < IN_DIM) ? Wq[(size_t)j * AD + a0 + a] * scale : 0.f;
        wqs[a][jj] = fpack(v, v);
    }
    __syncthreads();

    ull acc[4] = {0ULL, 0ULL, 0ULL, 0ULL};
    #pragma unroll 4
    for (int a = 0; a < ACHUNK; a++) {
        ull kp = *(const ull*)&ksm[a][2 * mp];
        double2 w01 = *(const double2*)&wqs[a][jg * 4];
        double2 w23 = *(const double2*)&wqs[a][jg * 4 + 2];
        acc[0] = ffma2(kp, d2u(w01.x), acc[0]);
        acc[1] = ffma2(kp, d2u(w01.y), acc[1]);
        acc[2] = ffma2(kp, d2u(w23.x), acc[2]);
        acc[3] = ffma2(kp, d2u(w23.y), acc[3]);
    }
    #pragma unroll
    for (int q = 0; q < 4; q++) {
        int j = j0 + jg * 4 + q;
        if (j < IN_DIM) {
            float2 v = funpack(acc[q]);
            atomicAdd(&g_KQT[j][2 * mp], v.x);
            atomicAdd(&g_KQT[j][2 * mp + 1], v.y);
        }
    }
}

// ---------------------------------------------------------------------------
// C1 (tensor core): dots = x @ KQ (M=32768, N=32, K=180 pad 192) via
// mma.m16n8k16 bf16 3-term split, then softmax over 32 slots, write w.
// (unchanged from the 125.2us run)
// ---------------------------------------------------------------------------
#define C1_SMEM 76800
__global__ __launch_bounds__(128, 2) void c1_kernel(const float* __restrict__ x,
                                                    float* __restrict__ w_out) {
    extern __shared__ u32 c1sm[];
    u32* xhi = c1sm;                 // [64][100]
    u32* xlo = c1sm + 6400;          // [64][100]
    u32* khi = c1sm + 12800;         // [32][100]
    u32* klo = c1sm + 16000;         // [32][100]

    const int row0 = blockIdx.x * 64;
    const int b = row0 >> 13;
    const int tid = threadIdx.x;

    for (int idx = tid; idx < 64 * 45; idx += 128) {
        int r = idx / 45, q = idx - r * 45;
        float4 v = *(const float4*)&x[(size_t)(row0 + r) * IN_DIM + q * 4];
        float h0 = bf16rt(v.x), h1 = bf16rt(v.y);
        float h2 = bf16rt(v.z), h3 = bf16rt(v.w);
        xhi[r * 100 + 2 * q]     = packbf2(h0, h1);
        xhi[r * 100 + 2 * q + 1] = packbf2(h2, h3);
        xlo[r * 100 + 2 * q]     = packbf2(v.x - h0, v.y - h1);
        xlo[r * 100 + 2 * q + 1] = packbf2(v.z - h2, v.w - h3);
    }
    for (int idx = tid; idx < 64 * 6; idx += 128) {
        int r = idx / 6, jp = 90 + idx - (idx / 6) * 6;
        xhi[r * 100 + jp] = 0u;
        xlo[r * 100 + jp] = 0u;
    }
    for (int idx = tid; idx < NS * 96; idx += 128) {
        int s = idx & 31, jp = idx >> 5;
        float f0 = (2 * jp     < IN_DIM) ? g_KQT[2 * jp][b * NS + s]     : 0.f;
        float f1 = (2 * jp + 1 < IN_DIM) ? g_KQT[2 * jp + 1][b * NS + s] : 0.f;
        float h0 = bf16rt(f0), h1 = bf16rt(f1);
        khi[s * 100 + jp] = packbf2(h0, h1);
        klo[s * 100 + jp] = packbf2(f0 - h0, f1 - h1);
    }
    __syncthreads();

    const int warp = tid >> 5, lane = tid & 31;
    const int gid = lane >> 2, tig = lane & 3;
    const int wr = warp * 16;

    float c[4][4];
    #pragma unroll
    for (int nt = 0; nt < 4; nt++)
        #pragma unroll
        for (int q = 0; q < 4; q++) c[nt][q] = 0.f;

    #pragma unroll
    for (int kt = 0; kt < 12; kt++) {
        const int pb = kt * 8;
        u32 Ah[4], Al[4];
        Ah[0] = xhi[(wr + gid    ) * 100 + pb + tig];
        Ah[1] = xhi[(wr + gid + 8) * 100 + pb + tig];
        Ah[2] = xhi[(wr + gid    ) * 100 + pb + tig + 4];
        Ah[3] = xhi[(wr + gid + 8) * 100 + pb + tig + 4];
        Al[0] = xlo[(wr + gid    ) * 100 + pb + tig];
        Al[1] = xlo[(wr + gid + 8) * 100 + pb + tig];
        Al[2] = xlo[(wr + gid    ) * 100 + pb + tig + 4];
        Al[3] = xlo[(wr + gid + 8) * 100 + pb + tig + 4];
        #pragma unroll
        for (int nt = 0; nt < 4; nt++) {
            const int n = nt * 8 + gid;
            u32 Bh[2] = { khi[n * 100 + pb + tig], khi[n * 100 + pb + tig + 4] };
            u32 Bl[2] = { klo[n * 100 + pb + tig], klo[n * 100 + pb + tig + 4] };
            mma16816(c[nt], Ah, Bh);
            mma16816(c[nt], Ah, Bl);
            mma16816(c[nt], Al, Bh);
        }
    }

    float m0 = -1e30f, m1 = -1e30f;
    #pragma unroll
    for (int nt = 0; nt < 4; nt++) {
        m0 = fmaxf(m0, fmaxf(c[nt][0], c[nt][1]));
        m1 = fmaxf(m1, fmaxf(c[nt][2], c[nt][3]));
    }
    m0 = fmaxf(m0, __shfl_xor_sync(0xffffffffu, m0, 1));
    m0 = fmaxf(m0, __shfl_xor_sync(0xffffffffu, m0, 2));
    m1 = fmaxf(m1, __shfl_xor_sync(0xffffffffu, m1, 1));
    m1 = fmaxf(m1, __shfl_xor_sync(0xffffffffu, m1, 2));

    float e[4][4];
    float s0 = 0.f, s1 = 0.f;
    #pragma unroll
    for (int nt = 0; nt < 4; nt++) {
        e[nt][0] = __expf(c[nt][0] - m0);
        e[nt][1] = __expf(c[nt][1] - m0);
        e[nt][2] = __expf(c[nt][2] - m1);
        e[nt][3] = __expf(c[nt][3] - m1);
        s0 += e[nt][0] + e[nt][1];
        s1 += e[nt][2] + e[nt][3];
    }
    s0 += __shfl_xor_sync(0xffffffffu, s0, 1);
    s0 += __shfl_xor_sync(0xffffffffu, s0, 2);
    s1 += __shfl_xor_sync(0xffffffffu, s1, 1);
    s1 += __shfl_xor_sync(0xffffffffu, s1, 2);
    float i0 = 1.0f / s0, i1 = 1.0f / s1;

    #pragma unroll
    for (int nt = 0; nt < 4; nt++) {
        const int n = nt * 8 + tig * 2;
        *(float2*)&w_out[(size_t)(row0 + wr + gid    ) * NS + n] =
            make_float2(e[nt][0] * i0, e[nt][1] * i0);
        *(float2*)&w_out[(size_t)(row0 + wr + gid + 8) * NS + n] =
            make_float2(e[nt][2] * i1, e[nt][3] * i1);
    }
}

// ---------------------------------------------------------------------------
// C2 (tensor core): s = w @ sl via mma.m16n8k16 bf16 3-term split.
// NEW: fragments staged in smem (stride 136 -> conflict-free), then fully
// coalesced STG.128 stores (512B contiguous per warp instruction).
// Dynamic smem 64KB: slT_hi/lo [128][20], whi/wlo [64][20], stage [64][136].
// ---------------------------------------------------------------------------
#define C2_SMEM 65536
__global__ __launch_bounds__(256, 3) void c2_kernel(const float* __restrict__ sl,
                                                    const float* __restrict__ w_in,
                                                    float* __restrict__ s_out) {
    extern __shared__ u32 c2sm[];
    u32*   slT_hi = c2sm;                    // [128][20]
    u32*   slT_lo = c2sm + 2560;             // [128][20]
    u32*   whi    = c2sm + 5120;             // [64][20]
    u32*   wlo    = c2sm + 6400;             // [64][20]
    float* stage  = (float*)(c2sm + 7680);   // [64][136]

    const int d0   = blockIdx.x * 128;
    const int row0 = blockIdx.y * 64;
    const int b    = row0 >> 13;
    const int tid  = threadIdx.x;

    #pragma unroll
    for (int t = 0; t < 8; t++) {
        int idx = t * 256 + tid;
        int q = idx >> 7, d = idx & 127;
        const float* base = &sl[(size_t)(b * NS + 2 * q) * SD + d0 + d];
        float v0 = base[0], v1 = base[SD];
        float h0 = bf16rt(v0), h1 = bf16rt(v1);
        slT_hi[d * 20 + q] = packbf2(h0, h1);
        slT_lo[d * 20 + q] = packbf2(v0 - h0, v1 - h1);
    }
    #pragma unroll
    for (int t = 0; t < 4; t++) {
        int idx = t * 256 + tid;
        int r = idx >> 4, q = idx & 15;
        const float* wb = &w_in[(size_t)(row0 + r) * NS + 2 * q];
        float v0 = wb[0], v1 = wb[1];
        float h0 = bf16rt(v0), h1 = bf16rt(v1);
        whi[r * 20 + q] = packbf2(h0, h1);
        wlo[r * 20 + q] = packbf2(v0 - h0, v1 - h1);
    }
    __syncthreads();

    const int warp = tid >> 5, lane = tid & 31;
    const int gid = lane >> 2, tig = lane & 3;
    const int wr = (warp >> 1) * 16;
    const int wd = (warp & 1) * 64;

    u32 Ahi[8], Alo[8];
    #pragma unroll
    for (int k = 0; k < 2; k++) {
        int pb = k * 8;
        Ahi[k*4+0] = whi[(wr + gid    ) * 20 + pb + tig    ];
        Ahi[k*4+1] = whi[(wr + gid + 8) * 20 + pb + tig    ];
        Ahi[k*4+2] = whi[(wr + gid    ) * 20 + pb + tig + 4];
        Ahi[k*4+3] = whi[(wr + gid + 8) * 20 + pb + tig + 4];
        Alo[k*4+0] = wlo[(wr + gid    ) * 20 + pb + tig    ];
        Alo[k*4+1] = wlo[(wr + gid + 8) * 20 + pb + tig    ];
        Alo[k*4+2] = wlo[(wr + gid    ) * 20 + pb + tig + 4];
        Alo[k*4+3] = wlo[(wr + gid + 8) * 20 + pb + tig + 4];
    }

    #pragma unroll
    for (int nt = 0; nt < 8; nt++) {
        const int dcol = wd + nt * 8 + gid;
        u32 Bh[4], Bl[4];
        Bh[0] = slT_hi[dcol * 20 + tig];      Bh[1] = slT_hi[dcol * 20 + tig + 4];
        Bh[2] = slT_hi[dcol * 20 + 8 + tig];  Bh[3] = slT_hi[dcol * 20 + 12 + tig];
        Bl[0] = slT_lo[dcol * 20 + tig];      Bl[1] = slT_lo[dcol * 20 + tig + 4];
        Bl[2] = slT_lo[dcol * 20 + 8 + tig];  Bl[3] = slT_lo[dcol * 20 + 12 + tig];

        float c[4] = {0.f, 0.f, 0.f, 0.f};
        mma16816(c, &Ahi[0], &Bh[0]);
        mma16816(c, &Ahi[4], &Bh[2]);
        mma16816(c, &Ahi[0], &Bl[0]);
        mma16816(c, &Ahi[4], &Bl[2]);
        mma16816(c, &Alo[0], &Bh[0]);
        mma16816(c, &Alo[4], &Bh[2]);

        const int dl = wd + nt * 8 + tig * 2;
        *(float2*)&stage[(wr + gid    ) * 136 + dl] = make_float2(c[0], c[1]);
        *(float2*)&stage[(wr + gid + 8) * 136 + dl] = make_float2(c[2], c[3]);
    }
    __syncthreads();

    // coalesced copy-out: warp reads one full row (LDS.128) and writes
    // contiguous 512B STG.128 per instruction.
    #pragma unroll
    for (int t = 0; t < 8; t++) {
        int idx = t * 256 + tid;
        int r = idx >> 5, dq = idx & 31;
        float4 v = *(const float4*)&stage[r * 136 + dq * 4];
        *(float4*)&s_out[(size_t)(row0 + r) * SD + d0 + dq * 4] = v;
    }
}

// ---------------------------------------------------------------------------
extern "C" void kernel_launch(void* const* d_in, const int* in_sizes, int n_in,
                              void* d_out, int out_size) {
    const float* x  = (const float*)d_in[0];   // [4,8192,180]
    const float* sl = (const float*)d_in[1];   // [4,32,1536]
    const float* Wq = (const float*)d_in[2];   // [180,1536]
    const float* Wk = (const float*)d_in[3];   // [1536,1536]
    float* out   = (float*)d_out;
    float* s_out = out;                               // [4,8192,1536]
    float* w_out = out + (size_t)NB * NR * SD;        // [4,8192,32]

    static int attr_done = 0;
    if (!attr_done) {
        cudaFuncSetAttribute(c1_kernel,
                             cudaFuncAttributeMaxDynamicSharedMemorySize, C1_SMEM);
        cudaFuncSetAttribute(c2_kernel,
                             cudaFuncAttributeMaxDynamicSharedMemorySize, C2_SMEM);
        attr_done = 1;
    }

    p1_kernel<<<dim3(AD / 256, BS / 32, KS), 128>>>(sl, Wk);
    p1r_kernel<<<(BS * AD / 4) / 256, 256>>>();
    p2_kernel<<<dim3(192 / JT, AC), 256>>>(Wq);
    c1_kernel<<<(NB * NR) / 64, 128, C1_SMEM>>>(x, w_out);
    c2_kernel<<<dim3(SD / 128, (NB * NR) / 64), 256, C2_SMEM>>>(sl, w_out, s_out);
}